// round 7
// baseline (speedup 1.0000x reference)
#include <cuda_runtime.h>
#include <cuda_bf16.h>
#include <math.h>
#include <stdint.h>
#include <string.h>

#define BATCH 4
#define CIN   256
#define HW    4096
#define DIM   64

typedef unsigned int u32;
typedef unsigned long long u64;

// ---------------------------------------------------------------------------
// Device scratch
// ---------------------------------------------------------------------------
__device__ __nv_bfloat16 g_xth[BATCH * HW * CIN];   // x transposed [b][n][c] hi
__device__ __nv_bfloat16 g_xtl[BATCH * HW * CIN];   // lo
__device__ __nv_bfloat16 g_wh[3 * DIM * CIN];       // wq|wk|wv hi
__device__ __nv_bfloat16 g_wl[3 * DIM * CIN];
__device__ __nv_bfloat16 g_wsah[CIN * DIM];
__device__ __nv_bfloat16 g_wsal[CIN * DIM];
__device__ __nv_bfloat16 g_qh[BATCH * HW * DIM];
__device__ __nv_bfloat16 g_ql[BATCH * HW * DIM];
__device__ __nv_bfloat16 g_kh[BATCH * HW * DIM];
__device__ __nv_bfloat16 g_kl[BATCH * HW * DIM];
__device__ __nv_bfloat16 g_vth[BATCH * DIM * HW];   // [b][d][j]
__device__ __nv_bfloat16 g_vtl[BATCH * DIM * HW];
__device__ __nv_bfloat16 g_sah[BATCH * HW * DIM];   // attention out [b][n][d]
__device__ __nv_bfloat16 g_sal[BATCH * HW * DIM];

// ---------------------------------------------------------------------------
// Helpers
// ---------------------------------------------------------------------------
__device__ __forceinline__ uint32_t smem_u32(const void* p) {
    uint32_t a;
    asm("{ .reg .u64 t; cvta.to.shared.u64 t, %1; cvt.u32.u64 %0, t; }" : "=r"(a) : "l"(p));
    return a;
}
// pack two floats into bf16x2: lo -> bits[15:0], hi -> bits[31:16]
__device__ __forceinline__ u32 packbf(float lo, float hi) {
    u32 r;
    asm("cvt.rn.bf16x2.f32 %0, %1, %2;" : "=r"(r) : "f"(hi), "f"(lo));
    return r;
}
__device__ __forceinline__ float2 unpackbf(u32 u) {
    __nv_bfloat162 h;
    memcpy(&h, &u, 4);
    return make_float2(__bfloat162float(h.x), __bfloat162float(h.y));
}
__device__ __forceinline__ void mma16816(float* c, const u32* a, const u32* b) {
    asm volatile(
        "mma.sync.aligned.m16n8k16.row.col.f32.bf16.bf16.f32 "
        "{%0,%1,%2,%3}, {%4,%5,%6,%7}, {%8,%9}, {%0,%1,%2,%3};"
        : "+f"(c[0]), "+f"(c[1]), "+f"(c[2]), "+f"(c[3])
        : "r"(a[0]), "r"(a[1]), "r"(a[2]), "r"(a[3]), "r"(b[0]), "r"(b[1]));
}
__device__ __forceinline__ void ldsm4(u32* r, uint32_t addr) {
    asm volatile("ldmatrix.sync.aligned.m8n8.x4.shared.b16 {%0,%1,%2,%3}, [%4];"
        : "=r"(r[0]), "=r"(r[1]), "=r"(r[2]), "=r"(r[3]) : "r"(addr));
}
__device__ __forceinline__ void ldsm2(u32* r, uint32_t addr) {
    asm volatile("ldmatrix.sync.aligned.m8n8.x2.shared.b16 {%0,%1}, [%2];"
        : "=r"(r[0]), "=r"(r[1]) : "r"(addr));
}
#define CP16(dst, src) asm volatile("cp.async.cg.shared.global [%0], [%1], 16;" :: "r"(dst), "l"(src))
#define CPC()  asm volatile("cp.async.commit_group;")
#define CPW0() asm volatile("cp.async.wait_group 0;")

// XOR swizzles for 128B / 256B / 512B rows (16B granules)
__device__ __forceinline__ u32 swz128(u32 row, u32 g) { return row * 128u + ((g ^ (row & 7u)) << 4); }
__device__ __forceinline__ u32 swz256(u32 row, u32 g) { return row * 256u + (((g & 8u) | ((g & 7u) ^ (row & 7u))) << 4); }
__device__ __forceinline__ u32 swz512(u32 row, u32 g) { return row * 512u + (((g & 24u) | ((g & 7u) ^ (row & 7u))) << 4); }

// ---------------------------------------------------------------------------
// Kernel 0a: x [b][c][n] fp32 -> xt hi/lo [b][n][c] bf16 (tile transpose)
// ---------------------------------------------------------------------------
__global__ __launch_bounds__(256) void convert_x_kernel(const float* __restrict__ x)
{
    __shared__ float xs[64][65];
    const int b  = blockIdx.z;
    const int c0 = blockIdx.y * 64;
    const int n0 = blockIdx.x * 64;
    const int tid = threadIdx.x;

#pragma unroll
    for (int i = 0; i < 4; i++) {
        int r = (tid >> 4) + i * 16;
        int col4 = (tid & 15) * 4;
        float4 v = *(const float4*)&x[(size_t)(b * CIN + c0 + r) * HW + n0 + col4];
        xs[r][col4 + 0] = v.x;
        xs[r][col4 + 1] = v.y;
        xs[r][col4 + 2] = v.z;
        xs[r][col4 + 3] = v.w;
    }
    __syncthreads();

    const int n  = tid >> 2;
    const int cs = (tid & 3) * 16;
    u32 hh[8], ll[8];
#pragma unroll
    for (int j = 0; j < 16; j += 2) {
        float a = xs[cs + j][n];
        float b2 = xs[cs + j + 1][n];
        u32 h = packbf(a, b2);
        float2 f = unpackbf(h);
        hh[j >> 1] = h;
        ll[j >> 1] = packbf(a - f.x, b2 - f.y);
    }
    size_t base = ((size_t)(b * HW) + n0 + n) * CIN + c0 + cs;
    *(uint4*)&g_xth[base]     = *(uint4*)&hh[0];
    *(uint4*)&g_xth[base + 8] = *(uint4*)&hh[4];
    *(uint4*)&g_xtl[base]     = *(uint4*)&ll[0];
    *(uint4*)&g_xtl[base + 8] = *(uint4*)&ll[4];
}

// ---------------------------------------------------------------------------
// Kernel 0b: weight conversion -> bf16 hi/lo
// ---------------------------------------------------------------------------
__global__ void convert_w_kernel(const float* __restrict__ wq, const float* __restrict__ wk,
                                 const float* __restrict__ wv, const float* __restrict__ wsa)
{
    const int p = blockIdx.x;
    const float* s = (p == 0) ? wq : (p == 1) ? wk : (p == 2) ? wv : wsa;
    __nv_bfloat16* dh = (p < 3) ? &g_wh[p * DIM * CIN] : g_wsah;
    __nv_bfloat16* dl = (p < 3) ? &g_wl[p * DIM * CIN] : g_wsal;
    for (int i = threadIdx.x; i < DIM * CIN; i += blockDim.x) {
        float v = s[i];
        __nv_bfloat16 h = __float2bfloat16(v);
        dh[i] = h;
        dl[i] = __float2bfloat16(v - __bfloat162float(h));
    }
}

// ---------------------------------------------------------------------------
// Kernel 1: QKV projections via HMMA hi/lo.
// out[n][d] = xt[n][c] . w[d][c]^T + bias.  M=128 (n), N=64 (d), K=256.
// ---------------------------------------------------------------------------
#define QKV_SMEM 196608

__global__ __launch_bounds__(256, 1) void qkv_mma_kernel(
    const float* __restrict__ bq, const float* __restrict__ bk, const float* __restrict__ bv)
{
    extern __shared__ char sm[];
    const u32 sb = smem_u32(sm);
    const int tid  = threadIdx.x;
    const int lane = tid & 31;
    const int wid  = tid >> 5;
    const int wm = wid & 3;
    const int wn = wid >> 2;
    const int g  = lane >> 2;
    const int t  = lane & 3;
    const int b  = blockIdx.y;
    const int p  = blockIdx.z;
    const int i0 = blockIdx.x * 128;
    const float* bias = (p == 0) ? bq : (p == 1) ? bk : bv;

    {
        const char* ah = (const char*)&g_xth[(size_t)(b * HW + i0) * CIN];
        const char* al = (const char*)&g_xtl[(size_t)(b * HW + i0) * CIN];
#pragma unroll
        for (int i = 0; i < 16; i++) {
            int id = tid + i * 256;
            u32 row = (u32)(id >> 5), gg = (u32)(id & 31);
            u32 o = swz512(row, gg);
            u32 so = row * 512 + gg * 16;
            CP16(sb + o, ah + so);
            CP16(sb + 65536 + o, al + so);
        }
        const char* bh = (const char*)&g_wh[p * DIM * CIN];
        const char* bl = (const char*)&g_wl[p * DIM * CIN];
#pragma unroll
        for (int i = 0; i < 8; i++) {
            int id = tid + i * 256;
            u32 row = (u32)(id >> 5), gg = (u32)(id & 31);
            u32 o = swz512(row, gg);
            u32 so = row * 512 + gg * 16;
            CP16(sb + 131072 + o, bh + so);
            CP16(sb + 163840 + o, bl + so);
        }
        CPC(); CPW0();
        __syncthreads();
    }

    float c[2][4][4];
#pragma unroll
    for (int mt = 0; mt < 2; mt++)
#pragma unroll
        for (int nt = 0; nt < 4; nt++)
#pragma unroll
            for (int e = 0; e < 4; e++) c[mt][nt][e] = 0.0f;

    const u32 a_row = wm * 32 + (lane & 15);
    const u32 a_g = (u32)(lane >> 4);
    const u32 b_row = wn * 32 + (lane & 7);
    const u32 b_g = (u32)((lane >> 3) & 1);

#pragma unroll
    for (int kt = 0; kt < 16; kt++) {
        u32 ah2[2][4], al2[2][4];
#pragma unroll
        for (int mt = 0; mt < 2; mt++) {
            u32 off = swz512(a_row + mt * 16, a_g + kt * 2);
            ldsm4(ah2[mt], sb + off);
            ldsm4(al2[mt], sb + 65536 + off);
        }
#pragma unroll
        for (int nt = 0; nt < 4; nt++) {
            u32 bh2[2], bl2[2];
            u32 off = swz512(b_row + nt * 8, b_g + kt * 2);
            ldsm2(bh2, sb + 131072 + off);
            ldsm2(bl2, sb + 163840 + off);
#pragma unroll
            for (int mt = 0; mt < 2; mt++) {
                mma16816(c[mt][nt], ah2[mt], bh2);
                mma16816(c[mt][nt], ah2[mt], bl2);
                mma16816(c[mt][nt], al2[mt], bh2);
            }
        }
    }

    if (p < 2) {
        __nv_bfloat16* oh = (p == 0) ? g_qh : g_kh;
        __nv_bfloat16* ol = (p == 0) ? g_ql : g_kl;
#pragma unroll
        for (int mt = 0; mt < 2; mt++)
#pragma unroll
            for (int nt = 0; nt < 4; nt++) {
                int n = i0 + wm * 32 + mt * 16 + g;
                int d = wn * 32 + nt * 8 + t * 2;
                float b0 = bias[d], b1 = bias[d + 1];
                float v0 = c[mt][nt][0] + b0, v1 = c[mt][nt][1] + b1;
                float v2 = c[mt][nt][2] + b0, v3 = c[mt][nt][3] + b1;
                u32 h01 = packbf(v0, v1); float2 f0 = unpackbf(h01);
                u32 l01 = packbf(v0 - f0.x, v1 - f0.y);
                u32 h23 = packbf(v2, v3); float2 f1 = unpackbf(h23);
                u32 l23 = packbf(v2 - f1.x, v3 - f1.y);
                size_t o0 = (size_t)(b * HW + n) * DIM + d;
                size_t o1 = (size_t)(b * HW + n + 8) * DIM + d;
                *(u32*)&oh[o0] = h01; *(u32*)&ol[o0] = l01;
                *(u32*)&oh[o1] = h23; *(u32*)&ol[o1] = l23;
            }
    } else {
        float* ot = (float*)sm;   // [64 d][128 n]
        __syncthreads();
#pragma unroll
        for (int mt = 0; mt < 2; mt++)
#pragma unroll
            for (int nt = 0; nt < 4; nt++) {
                int n = wm * 32 + mt * 16 + g;
                int d = wn * 32 + nt * 8 + t * 2;
                ot[d * 128 + n]           = c[mt][nt][0];
                ot[(d + 1) * 128 + n]     = c[mt][nt][1];
                ot[d * 128 + n + 8]       = c[mt][nt][2];
                ot[(d + 1) * 128 + n + 8] = c[mt][nt][3];
            }
        __syncthreads();
        int d  = tid >> 2;
        int ns = (tid & 3) * 32;
        float bvv = bias[d];
        u32 hh[16], ll[16];
#pragma unroll
        for (int j = 0; j < 32; j += 2) {
            float v0 = ot[d * 128 + ns + j] + bvv;
            float v1 = ot[d * 128 + ns + j + 1] + bvv;
            u32 h = packbf(v0, v1);
            float2 f = unpackbf(h);
            hh[j >> 1] = h;
            ll[j >> 1] = packbf(v0 - f.x, v1 - f.y);
        }
        size_t base = (size_t)(b * DIM + d) * HW + i0 + ns;
#pragma unroll
        for (int q4 = 0; q4 < 4; q4++) {
            *(uint4*)&g_vth[base + q4 * 8] = *(uint4*)&hh[q4 * 4];
            *(uint4*)&g_vtl[base + q4 * 8] = *(uint4*)&ll[q4 * 4];
        }
    }
}

// ---------------------------------------------------------------------------
// Kernel 2: HMMA flash attention. 512 threads = 16 warps (8 M-groups of 16
// rows x 2 j-halves of 64). 4 warps/SMSP for latency hiding; regs <= 128.
// Smem: Qh 0 | Ql 16K | buf0 32K..96K | buf1 96K..160K
// ---------------------------------------------------------------------------
#define SM_TOTAL 163840

__device__ __forceinline__ void load_kv(u32 sb, u32 bufbase, int b, int j0, int tid)
{
    const char* kh = (const char*)&g_kh[(size_t)(b * HW + j0) * DIM];
    const char* kl = (const char*)&g_kl[(size_t)(b * HW + j0) * DIM];
#pragma unroll
    for (int i = 0; i < 2; i++) {
        int id = tid + i * 512, row = id >> 3, g = id & 7;
        u32 o = swz128(row, g);
        u32 so = row * 128 + g * 16;
        CP16(sb + bufbase + o, kh + so);
        CP16(sb + bufbase + 16384 + o, kl + so);
    }
    const char* vh = (const char*)&g_vth[(size_t)b * DIM * HW + j0];
    const char* vl = (const char*)&g_vtl[(size_t)b * DIM * HW + j0];
#pragma unroll
    for (int i = 0; i < 2; i++) {
        int id = tid + i * 512, d = id >> 4, g = id & 15;
        u32 o = swz256(d, g);
        u32 so = d * (HW * 2) + g * 16;
        CP16(sb + bufbase + 32768 + o, vh + so);
        CP16(sb + bufbase + 49152 + o, vl + so);
    }
}

__global__ __launch_bounds__(512, 1) void attn_kernel()
{
    extern __shared__ char sm[];
    const u32 sb = smem_u32(sm);
    const int tid  = threadIdx.x;
    const int lane = tid & 31;
    const int wid  = tid >> 5;   // 0..15
    const int wm = wid & 7;      // M group: rows wm*16 .. +15
    const int wn = wid >> 3;     // j half:  cols wn*64 .. +63
    const int b  = blockIdx.y;
    const int i0 = blockIdx.x * 128;
    const int g  = lane >> 2;
    const int t  = lane & 3;

    {
        const char* qh = (const char*)&g_qh[(size_t)(b * HW + i0) * DIM];
        const char* ql = (const char*)&g_ql[(size_t)(b * HW + i0) * DIM];
#pragma unroll
        for (int i = 0; i < 2; i++) {
            int id = tid + i * 512, row = id >> 3, gg = id & 7;
            u32 o = swz128(row, gg);
            u32 so = row * 128 + gg * 16;
            CP16(sb + 0 + o, qh + so);
            CP16(sb + 16384 + o, ql + so);
        }
        load_kv(sb, 32768, b, 0, tid);
        CPC();
    }

    float oc[8][4];
    float lsum[2];
    lsum[0] = 0.0f; lsum[1] = 0.0f;
#pragma unroll
    for (int dnt = 0; dnt < 8; dnt++)
#pragma unroll
        for (int e = 0; e < 4; e++) oc[dnt][e] = 0.0f;

    const u32 q_row  = wm * 16 + (lane & 15);
    const u32 q_gsel = (u32)(lane >> 4);
    // x4 B-operand lane components: row-in-16-block + k-half granule
    const u32 b_ro = (u32)(((lane >> 4) << 3) + (lane & 7));
    const u32 b_gg = (u32)((lane >> 3) & 1);

    for (int jt = 0; jt < HW / 128; jt++) {
        CPW0();
        __syncthreads();
        const u32 buf = 32768 + (u32)(jt & 1) * 65536;
        if (jt + 1 < HW / 128)
            load_kv(sb, 32768 + (u32)((jt + 1) & 1) * 65536, b, (jt + 1) * 128, tid);
        CPC();

#pragma unroll
        for (int half = 0; half < 2; half++) {
            // ---- S for 32 j-cols ----
            float sc[4][4];
#pragma unroll
            for (int nt = 0; nt < 4; nt++)
#pragma unroll
                for (int e = 0; e < 4; e++) sc[nt][e] = 0.0f;

#pragma unroll
            for (int kt = 0; kt < 4; kt++) {
                u32 aqh[4], aql[4];
                {
                    u32 off = swz128(q_row, q_gsel + kt * 2);
                    ldsm4(aqh, sb + 0 + off);
                    ldsm4(aql, sb + 16384 + off);
                }
#pragma unroll
                for (int ntp = 0; ntp < 2; ntp++) {
                    u32 bh[4], bl[4];
                    u32 ro = (u32)(wn * 64 + half * 32 + ntp * 16) + b_ro;
                    u32 gg = b_gg + kt * 2;
                    u32 off = swz128(ro, gg);
                    ldsm4(bh, sb + buf + off);
                    ldsm4(bl, sb + buf + 16384 + off);
                    mma16816(sc[ntp * 2 + 0], aqh, bh + 0);
                    mma16816(sc[ntp * 2 + 0], aqh, bl + 0);
                    mma16816(sc[ntp * 2 + 0], aql, bh + 0);
                    mma16816(sc[ntp * 2 + 1], aqh, bh + 2);
                    mma16816(sc[ntp * 2 + 1], aqh, bl + 2);
                    mma16816(sc[ntp * 2 + 1], aql, bh + 2);
                }
            }

            // ---- softmax + PV in two 16-wide chunks ----
#pragma unroll
            for (int jj = 0; jj < 2; jj++) {
                const int jkt = half * 2 + jj;
                u32 ph[4], pl[4];
#pragma unroll
                for (int h = 0; h < 2; h++) {
                    int nt = jj * 2 + h;
                    float e0 = __expf(sc[nt][0]);
                    float e1 = __expf(sc[nt][1]);
                    float e2 = __expf(sc[nt][2]);
                    float e3 = __expf(sc[nt][3]);
                    lsum[0] += e0 + e1;
                    lsum[1] += e2 + e3;
                    u32 h01 = packbf(e0, e1);
                    u32 h23 = packbf(e2, e3);
                    ph[h * 2 + 0] = h01;
                    ph[h * 2 + 1] = h23;
                    float r0 = e0 - __uint_as_float(h01 << 16);
                    float r1 = e1 - __uint_as_float(h01 & 0xFFFF0000u);
                    float r2 = e2 - __uint_as_float(h23 << 16);
                    float r3 = e3 - __uint_as_float(h23 & 0xFFFF0000u);
                    pl[h * 2 + 0] = packbf(r0, r1);
                    pl[h * 2 + 1] = packbf(r2, r3);
                }
#pragma unroll
                for (int dntp = 0; dntp < 4; dntp++) {
                    u32 bvh[4], bvl[4];
                    u32 ro = (u32)(dntp * 16) + b_ro;
                    u32 gg = (u32)(wn * 8 + jkt * 2) + b_gg;
                    u32 off = swz256(ro, gg);
                    ldsm4(bvh, sb + buf + 32768 + off);
                    ldsm4(bvl, sb + buf + 49152 + off);
                    mma16816(oc[dntp * 2 + 0], ph, bvh + 0);
                    mma16816(oc[dntp * 2 + 0], ph, bvl + 0);
                    mma16816(oc[dntp * 2 + 0], pl, bvh + 0);
                    mma16816(oc[dntp * 2 + 1], ph, bvh + 2);
                    mma16816(oc[dntp * 2 + 1], ph, bvl + 2);
                    mma16816(oc[dntp * 2 + 1], pl, bvh + 2);
                }
            }
        }
        __syncthreads();
    }

    // ---- epilogue: combine j-half partials, normalize, store hi/lo bf16 ----
    float* lp = (float*)(sm + 65536);   // [wn][128]
#pragma unroll
    for (int r = 0; r < 2; r++) {
        float v = lsum[r];
        v += __shfl_xor_sync(0xffffffffu, v, 1);
        v += __shfl_xor_sync(0xffffffffu, v, 2);
        if (t == 0) lp[wn * 128 + wm * 16 + r * 8 + g] = v;
    }
    float* op = (float*)(sm + wn * 32768);
#pragma unroll
    for (int dnt = 0; dnt < 8; dnt++) {
        int r0 = wm * 16 + g;
        int c = dnt * 8 + t * 2;
        *(float2*)&op[r0 * 64 + c]       = make_float2(oc[dnt][0], oc[dnt][1]);
        *(float2*)&op[(r0 + 8) * 64 + c] = make_float2(oc[dnt][2], oc[dnt][3]);
    }
    __syncthreads();

    float* o0 = (float*)sm;
    float* o1 = (float*)(sm + 32768);
    float* lpf = (float*)(sm + 65536);
#pragma unroll
    for (int i = 0; i < 4; i++) {
        int idx = tid + i * 512;
        int row = idx >> 4, c4 = (idx & 15) * 4;
        float invl = 1.0f / (lpf[row] + lpf[128 + row]);
        float4 a = *(float4*)&o0[row * 64 + c4];
        float4 bb = *(float4*)&o1[row * 64 + c4];
        float v0 = (a.x + bb.x) * invl;
        float v1 = (a.y + bb.y) * invl;
        float v2 = (a.z + bb.z) * invl;
        float v3 = (a.w + bb.w) * invl;
        u32 h01 = packbf(v0, v1); float2 f0 = unpackbf(h01);
        u32 l01 = packbf(v0 - f0.x, v1 - f0.y);
        u32 h23 = packbf(v2, v3); float2 f1 = unpackbf(h23);
        u32 l23 = packbf(v2 - f1.x, v3 - f1.y);
        size_t off = (size_t)(b * HW + i0 + row) * DIM + c4;
        *(uint2*)&g_sah[off] = make_uint2(h01, h23);
        *(uint2*)&g_sal[off] = make_uint2(l01, l23);
    }
}

// ---------------------------------------------------------------------------
// Kernel 3: output projection via HMMA hi/lo + bias + gamma + residual.
// ---------------------------------------------------------------------------
#define PROJ_SMEM 65536

__global__ __launch_bounds__(256, 2) void proj_mma_kernel(
    const float* __restrict__ x,
    const float* __restrict__ bsa,
    const float* __restrict__ gamma,
    float* __restrict__ out)
{
    extern __shared__ char sm[];
    const u32 sb = smem_u32(sm);
    const int tid  = threadIdx.x;
    const int lane = tid & 31;
    const int wid  = tid >> 5;
    const int wm = wid & 3;
    const int wn = wid >> 2;
    const int g  = lane >> 2;
    const int t  = lane & 3;
    const int b  = blockIdx.z;
    const int c0 = blockIdx.y * 128;
    const int n0 = blockIdx.x * 128;

    {
        const char* ah = (const char*)&g_wsah[(size_t)c0 * DIM];
        const char* al = (const char*)&g_wsal[(size_t)c0 * DIM];
        const char* bh = (const char*)&g_sah[(size_t)(b * HW + n0) * DIM];
        const char* bl = (const char*)&g_sal[(size_t)(b * HW + n0) * DIM];
#pragma unroll
        for (int i = 0; i < 4; i++) {
            int id = tid + i * 256;
            u32 row = (u32)(id >> 3), gg = (u32)(id & 7);
            u32 o = swz128(row, gg);
            u32 so = row * 128 + gg * 16;
            CP16(sb + o, ah + so);
            CP16(sb + 16384 + o, al + so);
            CP16(sb + 32768 + o, bh + so);
            CP16(sb + 49152 + o, bl + so);
        }
        CPC(); CPW0();
        __syncthreads();
    }

    float c[2][8][4];
#pragma unroll
    for (int mt = 0; mt < 2; mt++)
#pragma unroll
        for (int nt = 0; nt < 8; nt++)
#pragma unroll
            for (int e = 0; e < 4; e++) c[mt][nt][e] = 0.0f;

    const u32 a_row = wm * 32 + (lane & 15);
    const u32 a_g = (u32)(lane >> 4);
    const u32 b_row = wn * 64 + (lane & 7);
    const u32 b_g = (u32)((lane >> 3) & 1);

#pragma unroll
    for (int kt = 0; kt < 4; kt++) {
        u32 ah2[2][4], al2[2][4];
#pragma unroll
        for (int mt = 0; mt < 2; mt++) {
            u32 off = swz128(a_row + mt * 16, a_g + kt * 2);
            ldsm4(ah2[mt], sb + off);
            ldsm4(al2[mt], sb + 16384 + off);
        }
#pragma unroll
        for (int nt = 0; nt < 8; nt++) {
            u32 bh2[2], bl2[2];
            u32 off = swz128(b_row + nt * 8, b_g + kt * 2);
            ldsm2(bh2, sb + 32768 + off);
            ldsm2(bl2, sb + 49152 + off);
#pragma unroll
            for (int mt = 0; mt < 2; mt++) {
                mma16816(c[mt][nt], ah2[mt], bh2);
                mma16816(c[mt][nt], ah2[mt], bl2);
                mma16816(c[mt][nt], al2[mt], bh2);
            }
        }
    }

    const float gm = gamma[0];
#pragma unroll
    for (int mt = 0; mt < 2; mt++)
#pragma unroll
        for (int nt = 0; nt < 8; nt++) {
            int cg = c0 + wm * 32 + mt * 16 + g;
            int n  = n0 + wn * 64 + nt * 8 + t * 2;
            float b0 = bsa[cg], b1 = bsa[cg + 8];
            size_t off0 = ((size_t)(b * CIN) + cg) * HW + n;
            size_t off1 = off0 + (size_t)8 * HW;
            float2 xv0 = *(const float2*)&x[off0];
            float2 xv1 = *(const float2*)&x[off1];
            float2 o0, o1;
            o0.x = gm * (c[mt][nt][0] + b0) + xv0.x;
            o0.y = gm * (c[mt][nt][1] + b0) + xv0.y;
            o1.x = gm * (c[mt][nt][2] + b1) + xv1.x;
            o1.y = gm * (c[mt][nt][3] + b1) + xv1.y;
            *(float2*)&out[off0] = o0;
            *(float2*)&out[off1] = o1;
        }
}

// ---------------------------------------------------------------------------
extern "C" void kernel_launch(void* const* d_in, const int* in_sizes, int n_in,
                              void* d_out, int out_size)
{
    const float* x     = (const float*)d_in[0];
    const float* wq    = (const float*)d_in[1];
    const float* bq    = (const float*)d_in[2];
    const float* wk    = (const float*)d_in[3];
    const float* bk    = (const float*)d_in[4];
    const float* wv    = (const float*)d_in[5];
    const float* bv    = (const float*)d_in[6];
    const float* wsa   = (const float*)d_in[7];
    const float* bsa   = (const float*)d_in[8];
    const float* gamma = (const float*)d_in[9];
    float* out = (float*)d_out;

    cudaFuncSetAttribute(attn_kernel, cudaFuncAttributeMaxDynamicSharedMemorySize, SM_TOTAL);
    cudaFuncSetAttribute(qkv_mma_kernel, cudaFuncAttributeMaxDynamicSharedMemorySize, QKV_SMEM);
    cudaFuncSetAttribute(proj_mma_kernel, cudaFuncAttributeMaxDynamicSharedMemorySize, PROJ_SMEM);

    convert_x_kernel<<<dim3(HW / 64, CIN / 64, BATCH), 256>>>(x);
    convert_w_kernel<<<4, 256>>>(wq, wk, wv, wsa);
    qkv_mma_kernel<<<dim3(HW / 128, BATCH, 3), 256, QKV_SMEM>>>(bq, bk, bv);
    attn_kernel<<<dim3(HW / 128, BATCH), 512, SM_TOTAL>>>();
    proj_mma_kernel<<<dim3(HW / 128, CIN / 128, BATCH), 256, PROJ_SMEM>>>(x, bsa, gamma, out);
}

// round 8
// speedup vs baseline: 1.1173x; 1.1173x over previous
#include <cuda_runtime.h>
#include <cuda_bf16.h>
#include <math.h>
#include <stdint.h>
#include <string.h>

#define BATCH 4
#define CIN   256
#define HW    4096
#define DIM   64

typedef unsigned int u32;
typedef unsigned long long u64;

// ---------------------------------------------------------------------------
// Device scratch
// ---------------------------------------------------------------------------
__device__ __nv_bfloat16 g_xth[BATCH * HW * CIN];   // x transposed [b][n][c] hi
__device__ __nv_bfloat16 g_xtl[BATCH * HW * CIN];   // lo
__device__ __nv_bfloat16 g_wh[3 * DIM * CIN];       // wq|wk|wv hi
__device__ __nv_bfloat16 g_wl[3 * DIM * CIN];
__device__ __nv_bfloat16 g_wsah[CIN * DIM];
__device__ __nv_bfloat16 g_wsal[CIN * DIM];
__device__ __nv_bfloat16 g_qh[BATCH * HW * DIM];
__device__ __nv_bfloat16 g_ql[BATCH * HW * DIM];
__device__ __nv_bfloat16 g_kh[BATCH * HW * DIM];
__device__ __nv_bfloat16 g_kl[BATCH * HW * DIM];
__device__ __nv_bfloat16 g_vth[BATCH * DIM * HW];   // [b][d][j] (hi only)
__device__ __nv_bfloat16 g_sah[BATCH * HW * DIM];   // attention out [b][n][d]
__device__ __nv_bfloat16 g_sal[BATCH * HW * DIM];

// ---------------------------------------------------------------------------
// Helpers
// ---------------------------------------------------------------------------
__device__ __forceinline__ uint32_t smem_u32(const void* p) {
    uint32_t a;
    asm("{ .reg .u64 t; cvta.to.shared.u64 t, %1; cvt.u32.u64 %0, t; }" : "=r"(a) : "l"(p));
    return a;
}
// pack two floats into bf16x2: lo -> bits[15:0], hi -> bits[31:16]
__device__ __forceinline__ u32 packbf(float lo, float hi) {
    u32 r;
    asm("cvt.rn.bf16x2.f32 %0, %1, %2;" : "=r"(r) : "f"(hi), "f"(lo));
    return r;
}
__device__ __forceinline__ float2 unpackbf(u32 u) {
    __nv_bfloat162 h;
    memcpy(&h, &u, 4);
    return make_float2(__bfloat162float(h.x), __bfloat162float(h.y));
}
__device__ __forceinline__ void mma16816(float* c, const u32* a, const u32* b) {
    asm volatile(
        "mma.sync.aligned.m16n8k16.row.col.f32.bf16.bf16.f32 "
        "{%0,%1,%2,%3}, {%4,%5,%6,%7}, {%8,%9}, {%0,%1,%2,%3};"
        : "+f"(c[0]), "+f"(c[1]), "+f"(c[2]), "+f"(c[3])
        : "r"(a[0]), "r"(a[1]), "r"(a[2]), "r"(a[3]), "r"(b[0]), "r"(b[1]));
}
__device__ __forceinline__ void ldsm4(u32* r, uint32_t addr) {
    asm volatile("ldmatrix.sync.aligned.m8n8.x4.shared.b16 {%0,%1,%2,%3}, [%4];"
        : "=r"(r[0]), "=r"(r[1]), "=r"(r[2]), "=r"(r[3]) : "r"(addr));
}
__device__ __forceinline__ void ldsm2(u32* r, uint32_t addr) {
    asm volatile("ldmatrix.sync.aligned.m8n8.x2.shared.b16 {%0,%1}, [%2];"
        : "=r"(r[0]), "=r"(r[1]) : "r"(addr));
}
#define CP16(dst, src) asm volatile("cp.async.cg.shared.global [%0], [%1], 16;" :: "r"(dst), "l"(src))
#define CPC()  asm volatile("cp.async.commit_group;")
#define CPW0() asm volatile("cp.async.wait_group 0;")

// XOR swizzles for 128B / 256B / 512B rows (16B granules)
__device__ __forceinline__ u32 swz128(u32 row, u32 g) { return row * 128u + ((g ^ (row & 7u)) << 4); }
__device__ __forceinline__ u32 swz256(u32 row, u32 g) { return row * 256u + (((g & 8u) | ((g & 7u) ^ (row & 7u))) << 4); }
__device__ __forceinline__ u32 swz512(u32 row, u32 g) { return row * 512u + (((g & 24u) | ((g & 7u) ^ (row & 7u))) << 4); }

// ---------------------------------------------------------------------------
// Kernel 0a: x [b][c][n] fp32 -> xt hi/lo [b][n][c] bf16 (tile transpose)
// ---------------------------------------------------------------------------
__global__ __launch_bounds__(256) void convert_x_kernel(const float* __restrict__ x)
{
    __shared__ float xs[64][65];
    const int b  = blockIdx.z;
    const int c0 = blockIdx.y * 64;
    const int n0 = blockIdx.x * 64;
    const int tid = threadIdx.x;

#pragma unroll
    for (int i = 0; i < 4; i++) {
        int r = (tid >> 4) + i * 16;
        int col4 = (tid & 15) * 4;
        float4 v = *(const float4*)&x[(size_t)(b * CIN + c0 + r) * HW + n0 + col4];
        xs[r][col4 + 0] = v.x;
        xs[r][col4 + 1] = v.y;
        xs[r][col4 + 2] = v.z;
        xs[r][col4 + 3] = v.w;
    }
    __syncthreads();

    const int n  = tid >> 2;
    const int cs = (tid & 3) * 16;
    u32 hh[8], ll[8];
#pragma unroll
    for (int j = 0; j < 16; j += 2) {
        float a = xs[cs + j][n];
        float b2 = xs[cs + j + 1][n];
        u32 h = packbf(a, b2);
        float2 f = unpackbf(h);
        hh[j >> 1] = h;
        ll[j >> 1] = packbf(a - f.x, b2 - f.y);
    }
    size_t base = ((size_t)(b * HW) + n0 + n) * CIN + c0 + cs;
    *(uint4*)&g_xth[base]     = *(uint4*)&hh[0];
    *(uint4*)&g_xth[base + 8] = *(uint4*)&hh[4];
    *(uint4*)&g_xtl[base]     = *(uint4*)&ll[0];
    *(uint4*)&g_xtl[base + 8] = *(uint4*)&ll[4];
}

// ---------------------------------------------------------------------------
// Kernel 0b: weight conversion -> bf16 hi/lo
// ---------------------------------------------------------------------------
__global__ void convert_w_kernel(const float* __restrict__ wq, const float* __restrict__ wk,
                                 const float* __restrict__ wv, const float* __restrict__ wsa)
{
    const int p = blockIdx.x;
    const float* s = (p == 0) ? wq : (p == 1) ? wk : (p == 2) ? wv : wsa;
    __nv_bfloat16* dh = (p < 3) ? &g_wh[p * DIM * CIN] : g_wsah;
    __nv_bfloat16* dl = (p < 3) ? &g_wl[p * DIM * CIN] : g_wsal;
    for (int i = threadIdx.x; i < DIM * CIN; i += blockDim.x) {
        float v = s[i];
        __nv_bfloat16 h = __float2bfloat16(v);
        dh[i] = h;
        dl[i] = __float2bfloat16(v - __bfloat162float(h));
    }
}

// ---------------------------------------------------------------------------
// Kernel 1: QKV projections via HMMA hi/lo.
// out[n][d] = xt[n][c] . w[d][c]^T + bias.  M=128 (n), N=64 (d), K=256.
// ---------------------------------------------------------------------------
#define QKV_SMEM 196608

__global__ __launch_bounds__(256, 1) void qkv_mma_kernel(
    const float* __restrict__ bq, const float* __restrict__ bk, const float* __restrict__ bv)
{
    extern __shared__ char sm[];
    const u32 sb = smem_u32(sm);
    const int tid  = threadIdx.x;
    const int lane = tid & 31;
    const int wid  = tid >> 5;
    const int wm = wid & 3;
    const int wn = wid >> 2;
    const int g  = lane >> 2;
    const int t  = lane & 3;
    const int b  = blockIdx.y;
    const int p  = blockIdx.z;
    const int i0 = blockIdx.x * 128;
    const float* bias = (p == 0) ? bq : (p == 1) ? bk : bv;

    {
        const char* ah = (const char*)&g_xth[(size_t)(b * HW + i0) * CIN];
        const char* al = (const char*)&g_xtl[(size_t)(b * HW + i0) * CIN];
#pragma unroll
        for (int i = 0; i < 16; i++) {
            int id = tid + i * 256;
            u32 row = (u32)(id >> 5), gg = (u32)(id & 31);
            u32 o = swz512(row, gg);
            u32 so = row * 512 + gg * 16;
            CP16(sb + o, ah + so);
            CP16(sb + 65536 + o, al + so);
        }
        const char* bh = (const char*)&g_wh[p * DIM * CIN];
        const char* bl = (const char*)&g_wl[p * DIM * CIN];
#pragma unroll
        for (int i = 0; i < 8; i++) {
            int id = tid + i * 256;
            u32 row = (u32)(id >> 5), gg = (u32)(id & 31);
            u32 o = swz512(row, gg);
            u32 so = row * 512 + gg * 16;
            CP16(sb + 131072 + o, bh + so);
            CP16(sb + 163840 + o, bl + so);
        }
        CPC(); CPW0();
        __syncthreads();
    }

    float c[2][4][4];
#pragma unroll
    for (int mt = 0; mt < 2; mt++)
#pragma unroll
        for (int nt = 0; nt < 4; nt++)
#pragma unroll
            for (int e = 0; e < 4; e++) c[mt][nt][e] = 0.0f;

    const u32 a_row = wm * 32 + (lane & 15);
    const u32 a_g = (u32)(lane >> 4);
    const u32 b_row = wn * 32 + (lane & 7);
    const u32 b_g = (u32)((lane >> 3) & 1);

#pragma unroll
    for (int kt = 0; kt < 16; kt++) {
        u32 ah2[2][4], al2[2][4];
#pragma unroll
        for (int mt = 0; mt < 2; mt++) {
            u32 off = swz512(a_row + mt * 16, a_g + kt * 2);
            ldsm4(ah2[mt], sb + off);
            ldsm4(al2[mt], sb + 65536 + off);
        }
#pragma unroll
        for (int nt = 0; nt < 4; nt++) {
            u32 bh2[2], bl2[2];
            u32 off = swz512(b_row + nt * 8, b_g + kt * 2);
            ldsm2(bh2, sb + 131072 + off);
            ldsm2(bl2, sb + 163840 + off);
#pragma unroll
            for (int mt = 0; mt < 2; mt++) {
                mma16816(c[mt][nt], ah2[mt], bh2);
                mma16816(c[mt][nt], ah2[mt], bl2);
                mma16816(c[mt][nt], al2[mt], bh2);
            }
        }
    }

    if (p < 2) {
        __nv_bfloat16* oh = (p == 0) ? g_qh : g_kh;
        __nv_bfloat16* ol = (p == 0) ? g_ql : g_kl;
#pragma unroll
        for (int mt = 0; mt < 2; mt++)
#pragma unroll
            for (int nt = 0; nt < 4; nt++) {
                int n = i0 + wm * 32 + mt * 16 + g;
                int d = wn * 32 + nt * 8 + t * 2;
                float b0 = bias[d], b1 = bias[d + 1];
                float v0 = c[mt][nt][0] + b0, v1 = c[mt][nt][1] + b1;
                float v2 = c[mt][nt][2] + b0, v3 = c[mt][nt][3] + b1;
                u32 h01 = packbf(v0, v1); float2 f0 = unpackbf(h01);
                u32 l01 = packbf(v0 - f0.x, v1 - f0.y);
                u32 h23 = packbf(v2, v3); float2 f1 = unpackbf(h23);
                u32 l23 = packbf(v2 - f1.x, v3 - f1.y);
                size_t o0 = (size_t)(b * HW + n) * DIM + d;
                size_t o1 = (size_t)(b * HW + n + 8) * DIM + d;
                *(u32*)&oh[o0] = h01; *(u32*)&ol[o0] = l01;
                *(u32*)&oh[o1] = h23; *(u32*)&ol[o1] = l23;
            }
    } else {
        // v: bounce through smem, store hi only (PV uses 2-term (ph+pl)*vh)
        float* ot = (float*)sm;   // [64 d][128 n]
        __syncthreads();
#pragma unroll
        for (int mt = 0; mt < 2; mt++)
#pragma unroll
            for (int nt = 0; nt < 4; nt++) {
                int n = wm * 32 + mt * 16 + g;
                int d = wn * 32 + nt * 8 + t * 2;
                ot[d * 128 + n]           = c[mt][nt][0];
                ot[(d + 1) * 128 + n]     = c[mt][nt][1];
                ot[d * 128 + n + 8]       = c[mt][nt][2];
                ot[(d + 1) * 128 + n + 8] = c[mt][nt][3];
            }
        __syncthreads();
        int d  = tid >> 2;
        int ns = (tid & 3) * 32;
        float bvv = bias[d];
        u32 hh[16];
#pragma unroll
        for (int j = 0; j < 32; j += 2) {
            float v0 = ot[d * 128 + ns + j] + bvv;
            float v1 = ot[d * 128 + ns + j + 1] + bvv;
            hh[j >> 1] = packbf(v0, v1);
        }
        size_t base = (size_t)(b * DIM + d) * HW + i0 + ns;
#pragma unroll
        for (int q4 = 0; q4 < 4; q4++)
            *(uint4*)&g_vth[base + q4 * 8] = *(uint4*)&hh[q4 * 4];
    }
}

// ---------------------------------------------------------------------------
// Kernel 2: HMMA flash attention. 512 threads = 16 warps (8 M x 2 j-halves).
// PV is 2-term: O += (ph + pl) * vh  (V lo residual dropped; linear path).
// Smem: Qh 0 (16K) | Ql 16K | buf0 32K..80K | buf1 80K..128K
//   buf: Kh +0 (16K), Kl +16K, Vh +32K  (48KB per buffer)
// ---------------------------------------------------------------------------
#define ATT_BUF0   32768
#define ATT_BUFSZ  49152
#define SM_TOTAL   131072

__device__ __forceinline__ void load_kv(u32 sb, u32 bufbase, int b, int j0, int tid)
{
    const char* kh = (const char*)&g_kh[(size_t)(b * HW + j0) * DIM];
    const char* kl = (const char*)&g_kl[(size_t)(b * HW + j0) * DIM];
#pragma unroll
    for (int i = 0; i < 2; i++) {
        int id = tid + i * 512, row = id >> 3, g = id & 7;
        u32 o = swz128(row, g);
        u32 so = row * 128 + g * 16;
        CP16(sb + bufbase + o, kh + so);
        CP16(sb + bufbase + 16384 + o, kl + so);
    }
    const char* vh = (const char*)&g_vth[(size_t)b * DIM * HW + j0];
#pragma unroll
    for (int i = 0; i < 2; i++) {
        int id = tid + i * 512, d = id >> 4, g = id & 15;
        u32 o = swz256(d, g);
        u32 so = d * (HW * 2) + g * 16;
        CP16(sb + bufbase + 32768 + o, vh + so);
    }
}

__global__ __launch_bounds__(512, 1) void attn_kernel()
{
    extern __shared__ char sm[];
    const u32 sb = smem_u32(sm);
    const int tid  = threadIdx.x;
    const int lane = tid & 31;
    const int wid  = tid >> 5;   // 0..15
    const int wm = wid & 7;      // M group: rows wm*16 .. +15
    const int wn = wid >> 3;     // j half:  cols wn*64 .. +63
    const int b  = blockIdx.y;
    const int i0 = blockIdx.x * 128;
    const int g  = lane >> 2;
    const int t  = lane & 3;

    {
        const char* qh = (const char*)&g_qh[(size_t)(b * HW + i0) * DIM];
        const char* ql = (const char*)&g_ql[(size_t)(b * HW + i0) * DIM];
#pragma unroll
        for (int i = 0; i < 2; i++) {
            int id = tid + i * 512, row = id >> 3, gg = id & 7;
            u32 o = swz128(row, gg);
            u32 so = row * 128 + gg * 16;
            CP16(sb + 0 + o, qh + so);
            CP16(sb + 16384 + o, ql + so);
        }
        load_kv(sb, ATT_BUF0, b, 0, tid);
        CPC();
    }

    float oc[8][4];
    float lsum[2];
    lsum[0] = 0.0f; lsum[1] = 0.0f;
#pragma unroll
    for (int dnt = 0; dnt < 8; dnt++)
#pragma unroll
        for (int e = 0; e < 4; e++) oc[dnt][e] = 0.0f;

    const u32 q_row  = wm * 16 + (lane & 15);
    const u32 q_gsel = (u32)(lane >> 4);
    const u32 b_ro = (u32)(((lane >> 4) << 3) + (lane & 7));
    const u32 b_gg = (u32)((lane >> 3) & 1);

    for (int jt = 0; jt < HW / 128; jt++) {
        CPW0();
        __syncthreads();
        const u32 buf = ATT_BUF0 + (u32)(jt & 1) * ATT_BUFSZ;
        if (jt + 1 < HW / 128)
            load_kv(sb, ATT_BUF0 + (u32)((jt + 1) & 1) * ATT_BUFSZ, b, (jt + 1) * 128, tid);
        CPC();

#pragma unroll
        for (int half = 0; half < 2; half++) {
            // ---- S for 32 j-cols ----
            float sc[4][4];
#pragma unroll
            for (int nt = 0; nt < 4; nt++)
#pragma unroll
                for (int e = 0; e < 4; e++) sc[nt][e] = 0.0f;

#pragma unroll
            for (int kt = 0; kt < 4; kt++) {
                u32 aqh[4], aql[4];
                {
                    u32 off = swz128(q_row, q_gsel + kt * 2);
                    ldsm4(aqh, sb + 0 + off);
                    ldsm4(aql, sb + 16384 + off);
                }
#pragma unroll
                for (int ntp = 0; ntp < 2; ntp++) {
                    u32 bh[4], bl[4];
                    u32 ro = (u32)(wn * 64 + half * 32 + ntp * 16) + b_ro;
                    u32 gg = b_gg + kt * 2;
                    u32 off = swz128(ro, gg);
                    ldsm4(bh, sb + buf + off);
                    ldsm4(bl, sb + buf + 16384 + off);
                    mma16816(sc[ntp * 2 + 0], aqh, bh + 0);
                    mma16816(sc[ntp * 2 + 0], aqh, bl + 0);
                    mma16816(sc[ntp * 2 + 0], aql, bh + 0);
                    mma16816(sc[ntp * 2 + 1], aqh, bh + 2);
                    mma16816(sc[ntp * 2 + 1], aqh, bl + 2);
                    mma16816(sc[ntp * 2 + 1], aql, bh + 2);
                }
            }

            // ---- softmax + PV in two 16-wide chunks ----
#pragma unroll
            for (int jj = 0; jj < 2; jj++) {
                const int jkt = half * 2 + jj;
                u32 ph[4], pl[4];
#pragma unroll
                for (int h = 0; h < 2; h++) {
                    int nt = jj * 2 + h;
                    float e0 = __expf(sc[nt][0]);
                    float e1 = __expf(sc[nt][1]);
                    float e2 = __expf(sc[nt][2]);
                    float e3 = __expf(sc[nt][3]);
                    lsum[0] += e0 + e1;
                    lsum[1] += e2 + e3;
                    u32 h01 = packbf(e0, e1);
                    u32 h23 = packbf(e2, e3);
                    ph[h * 2 + 0] = h01;
                    ph[h * 2 + 1] = h23;
                    float r0 = e0 - __uint_as_float(h01 << 16);
                    float r1 = e1 - __uint_as_float(h01 & 0xFFFF0000u);
                    float r2 = e2 - __uint_as_float(h23 << 16);
                    float r3 = e3 - __uint_as_float(h23 & 0xFFFF0000u);
                    pl[h * 2 + 0] = packbf(r0, r1);
                    pl[h * 2 + 1] = packbf(r2, r3);
                }
#pragma unroll
                for (int dntp = 0; dntp < 4; dntp++) {
                    u32 bvh[4];
                    u32 ro = (u32)(dntp * 16) + b_ro;
                    u32 gg = (u32)(wn * 8 + jkt * 2) + b_gg;
                    u32 off = swz256(ro, gg);
                    ldsm4(bvh, sb + buf + 32768 + off);
                    mma16816(oc[dntp * 2 + 0], ph, bvh + 0);
                    mma16816(oc[dntp * 2 + 0], pl, bvh + 0);
                    mma16816(oc[dntp * 2 + 1], ph, bvh + 2);
                    mma16816(oc[dntp * 2 + 1], pl, bvh + 2);
                }
            }
        }
        // no bottom barrier: the top barrier of jt+1 orders buffer reuse
    }
    __syncthreads();   // protect smem-reuse writes below against last-tile reads

    // ---- epilogue: combine j-half partials, normalize, store hi/lo bf16 ----
    float* lp = (float*)(sm + 65536);   // [wn][128]
#pragma unroll
    for (int r = 0; r < 2; r++) {
        float v = lsum[r];
        v += __shfl_xor_sync(0xffffffffu, v, 1);
        v += __shfl_xor_sync(0xffffffffu, v, 2);
        if (t == 0) lp[wn * 128 + wm * 16 + r * 8 + g] = v;
    }
    float* op = (float*)(sm + wn * 32768);
#pragma unroll
    for (int dnt = 0; dnt < 8; dnt++) {
        int r0 = wm * 16 + g;
        int c = dnt * 8 + t * 2;
        *(float2*)&op[r0 * 64 + c]       = make_float2(oc[dnt][0], oc[dnt][1]);
        *(float2*)&op[(r0 + 8) * 64 + c] = make_float2(oc[dnt][2], oc[dnt][3]);
    }
    __syncthreads();

    float* o0 = (float*)sm;
    float* o1 = (float*)(sm + 32768);
    float* lpf = (float*)(sm + 65536);
#pragma unroll
    for (int i = 0; i < 4; i++) {
        int idx = tid + i * 512;
        int row = idx >> 4, c4 = (idx & 15) * 4;
        float invl = 1.0f / (lpf[row] + lpf[128 + row]);
        float4 a = *(float4*)&o0[row * 64 + c4];
        float4 bb = *(float4*)&o1[row * 64 + c4];
        float v0 = (a.x + bb.x) * invl;
        float v1 = (a.y + bb.y) * invl;
        float v2 = (a.z + bb.z) * invl;
        float v3 = (a.w + bb.w) * invl;
        u32 h01 = packbf(v0, v1); float2 f0 = unpackbf(h01);
        u32 l01 = packbf(v0 - f0.x, v1 - f0.y);
        u32 h23 = packbf(v2, v3); float2 f1 = unpackbf(h23);
        u32 l23 = packbf(v2 - f1.x, v3 - f1.y);
        size_t off = (size_t)(b * HW + i0 + row) * DIM + c4;
        *(uint2*)&g_sah[off] = make_uint2(h01, h23);
        *(uint2*)&g_sal[off] = make_uint2(l01, l23);
    }
}

// ---------------------------------------------------------------------------
// Kernel 3: output projection via HMMA hi/lo + bias + gamma + residual.
// ---------------------------------------------------------------------------
#define PROJ_SMEM 65536

__global__ __launch_bounds__(256, 2) void proj_mma_kernel(
    const float* __restrict__ x,
    const float* __restrict__ bsa,
    const float* __restrict__ gamma,
    float* __restrict__ out)
{
    extern __shared__ char sm[];
    const u32 sb = smem_u32(sm);
    const int tid  = threadIdx.x;
    const int lane = tid & 31;
    const int wid  = tid >> 5;
    const int wm = wid & 3;
    const int wn = wid >> 2;
    const int g  = lane >> 2;
    const int t  = lane & 3;
    const int b  = blockIdx.z;
    const int c0 = blockIdx.y * 128;
    const int n0 = blockIdx.x * 128;

    {
        const char* ah = (const char*)&g_wsah[(size_t)c0 * DIM];
        const char* al = (const char*)&g_wsal[(size_t)c0 * DIM];
        const char* bh = (const char*)&g_sah[(size_t)(b * HW + n0) * DIM];
        const char* bl = (const char*)&g_sal[(size_t)(b * HW + n0) * DIM];
#pragma unroll
        for (int i = 0; i < 4; i++) {
            int id = tid + i * 256;
            u32 row = (u32)(id >> 3), gg = (u32)(id & 7);
            u32 o = swz128(row, gg);
            u32 so = row * 128 + gg * 16;
            CP16(sb + o, ah + so);
            CP16(sb + 16384 + o, al + so);
            CP16(sb + 32768 + o, bh + so);
            CP16(sb + 49152 + o, bl + so);
        }
        CPC(); CPW0();
        __syncthreads();
    }

    float c[2][8][4];
#pragma unroll
    for (int mt = 0; mt < 2; mt++)
#pragma unroll
        for (int nt = 0; nt < 8; nt++)
#pragma unroll
            for (int e = 0; e < 4; e++) c[mt][nt][e] = 0.0f;

    const u32 a_row = wm * 32 + (lane & 15);
    const u32 a_g = (u32)(lane >> 4);
    const u32 b_row = wn * 64 + (lane & 7);
    const u32 b_g = (u32)((lane >> 3) & 1);

#pragma unroll
    for (int kt = 0; kt < 4; kt++) {
        u32 ah2[2][4], al2[2][4];
#pragma unroll
        for (int mt = 0; mt < 2; mt++) {
            u32 off = swz128(a_row + mt * 16, a_g + kt * 2);
            ldsm4(ah2[mt], sb + off);
            ldsm4(al2[mt], sb + 16384 + off);
        }
#pragma unroll
        for (int nt = 0; nt < 8; nt++) {
            u32 bh2[2], bl2[2];
            u32 off = swz128(b_row + nt * 8, b_g + kt * 2);
            ldsm2(bh2, sb + 32768 + off);
            ldsm2(bl2, sb + 49152 + off);
#pragma unroll
            for (int mt = 0; mt < 2; mt++) {
                mma16816(c[mt][nt], ah2[mt], bh2);
                mma16816(c[mt][nt], ah2[mt], bl2);
                mma16816(c[mt][nt], al2[mt], bh2);
            }
        }
    }

    const float gm = gamma[0];
#pragma unroll
    for (int mt = 0; mt < 2; mt++)
#pragma unroll
        for (int nt = 0; nt < 8; nt++) {
            int cg = c0 + wm * 32 + mt * 16 + g;
            int n  = n0 + wn * 64 + nt * 8 + t * 2;
            float b0 = bsa[cg], b1 = bsa[cg + 8];
            size_t off0 = ((size_t)(b * CIN) + cg) * HW + n;
            size_t off1 = off0 + (size_t)8 * HW;
            float2 xv0 = *(const float2*)&x[off0];
            float2 xv1 = *(const float2*)&x[off1];
            float2 o0, o1;
            o0.x = gm * (c[mt][nt][0] + b0) + xv0.x;
            o0.y = gm * (c[mt][nt][1] + b0) + xv0.y;
            o1.x = gm * (c[mt][nt][2] + b1) + xv1.x;
            o1.y = gm * (c[mt][nt][3] + b1) + xv1.y;
            *(float2*)&out[off0] = o0;
            *(float2*)&out[off1] = o1;
        }
}

// ---------------------------------------------------------------------------
extern "C" void kernel_launch(void* const* d_in, const int* in_sizes, int n_in,
                              void* d_out, int out_size)
{
    const float* x     = (const float*)d_in[0];
    const float* wq    = (const float*)d_in[1];
    const float* bq    = (const float*)d_in[2];
    const float* wk    = (const float*)d_in[3];
    const float* bk    = (const float*)d_in[4];
    const float* wv    = (const float*)d_in[5];
    const float* bv    = (const float*)d_in[6];
    const float* wsa   = (const float*)d_in[7];
    const float* bsa   = (const float*)d_in[8];
    const float* gamma = (const float*)d_in[9];
    float* out = (float*)d_out;

    cudaFuncSetAttribute(attn_kernel, cudaFuncAttributeMaxDynamicSharedMemorySize, SM_TOTAL);
    cudaFuncSetAttribute(qkv_mma_kernel, cudaFuncAttributeMaxDynamicSharedMemorySize, QKV_SMEM);
    cudaFuncSetAttribute(proj_mma_kernel, cudaFuncAttributeMaxDynamicSharedMemorySize, PROJ_SMEM);

    convert_x_kernel<<<dim3(HW / 64, CIN / 64, BATCH), 256>>>(x);
    convert_w_kernel<<<4, 256>>>(wq, wk, wv, wsa);
    qkv_mma_kernel<<<dim3(HW / 128, BATCH, 3), 256, QKV_SMEM>>>(bq, bk, bv);
    attn_kernel<<<dim3(HW / 128, BATCH), 512, SM_TOTAL>>>();
    proj_mma_kernel<<<dim3(HW / 128, CIN / 128, BATCH), 256, PROJ_SMEM>>>(x, bsa, gamma, out);
}

// round 9
// speedup vs baseline: 1.2948x; 1.1588x over previous
#include <cuda_runtime.h>
#include <cuda_bf16.h>
#include <math.h>
#include <stdint.h>
#include <string.h>

#define BATCH 4
#define CIN   256
#define HW    4096
#define DIM   64
#define LOG2E 1.4426950408889634f

typedef unsigned int u32;
typedef unsigned long long u64;

// ---------------------------------------------------------------------------
// Device scratch
// ---------------------------------------------------------------------------
__device__ __nv_bfloat16 g_xth[BATCH * HW * CIN];   // x transposed [b][n][c] hi
__device__ __nv_bfloat16 g_xtl[BATCH * HW * CIN];   // lo
__device__ __nv_bfloat16 g_wh[3 * DIM * CIN];       // wq|wk|wv hi
__device__ __nv_bfloat16 g_wl[3 * DIM * CIN];
__device__ __nv_bfloat16 g_wsah[CIN * DIM];
__device__ __nv_bfloat16 g_wsal[CIN * DIM];
__device__ __nv_bfloat16 g_qh[BATCH * HW * DIM];    // q pre-scaled by log2(e)
__device__ __nv_bfloat16 g_ql[BATCH * HW * DIM];
__device__ __nv_bfloat16 g_kh[BATCH * HW * DIM];
__device__ __nv_bfloat16 g_kl[BATCH * HW * DIM];
__device__ __nv_bfloat16 g_vth[BATCH * DIM * HW];   // [b][d][j] (hi only)
__device__ __nv_bfloat16 g_sah[BATCH * HW * DIM];   // attention out [b][n][d]
__device__ __nv_bfloat16 g_sal[BATCH * HW * DIM];

// ---------------------------------------------------------------------------
// Helpers
// ---------------------------------------------------------------------------
__device__ __forceinline__ uint32_t smem_u32(const void* p) {
    uint32_t a;
    asm("{ .reg .u64 t; cvta.to.shared.u64 t, %1; cvt.u32.u64 %0, t; }" : "=r"(a) : "l"(p));
    return a;
}
// pack two floats into bf16x2: lo -> bits[15:0], hi -> bits[31:16]
__device__ __forceinline__ u32 packbf(float lo, float hi) {
    u32 r;
    asm("cvt.rn.bf16x2.f32 %0, %1, %2;" : "=r"(r) : "f"(hi), "f"(lo));
    return r;
}
__device__ __forceinline__ float2 unpackbf(u32 u) {
    __nv_bfloat162 h;
    memcpy(&h, &u, 4);
    return make_float2(__bfloat162float(h.x), __bfloat162float(h.y));
}
__device__ __forceinline__ float ex2f(float x) {
    float r;
    asm("ex2.approx.f32 %0, %1;" : "=f"(r) : "f"(x));
    return r;
}
__device__ __forceinline__ void mma16816(float* c, const u32* a, const u32* b) {
    asm volatile(
        "mma.sync.aligned.m16n8k16.row.col.f32.bf16.bf16.f32 "
        "{%0,%1,%2,%3}, {%4,%5,%6,%7}, {%8,%9}, {%0,%1,%2,%3};"
        : "+f"(c[0]), "+f"(c[1]), "+f"(c[2]), "+f"(c[3])
        : "r"(a[0]), "r"(a[1]), "r"(a[2]), "r"(a[3]), "r"(b[0]), "r"(b[1]));
}
__device__ __forceinline__ void ldsm4(u32* r, uint32_t addr) {
    asm volatile("ldmatrix.sync.aligned.m8n8.x4.shared.b16 {%0,%1,%2,%3}, [%4];"
        : "=r"(r[0]), "=r"(r[1]), "=r"(r[2]), "=r"(r[3]) : "r"(addr));
}
__device__ __forceinline__ void ldsm2(u32* r, uint32_t addr) {
    asm volatile("ldmatrix.sync.aligned.m8n8.x2.shared.b16 {%0,%1}, [%2];"
        : "=r"(r[0]), "=r"(r[1]) : "r"(addr));
}
#define CP16(dst, src) asm volatile("cp.async.cg.shared.global [%0], [%1], 16;" :: "r"(dst), "l"(src))
#define CPC()  asm volatile("cp.async.commit_group;")
#define CPW0() asm volatile("cp.async.wait_group 0;")

// XOR swizzles for 128B / 256B / 512B rows (16B granules)
__device__ __forceinline__ u32 swz128(u32 row, u32 g) { return row * 128u + ((g ^ (row & 7u)) << 4); }
__device__ __forceinline__ u32 swz256(u32 row, u32 g) { return row * 256u + (((g & 8u) | ((g & 7u) ^ (row & 7u))) << 4); }
__device__ __forceinline__ u32 swz512(u32 row, u32 g) { return row * 512u + (((g & 24u) | ((g & 7u) ^ (row & 7u))) << 4); }

// ---------------------------------------------------------------------------
// Kernel 0a: x [b][c][n] fp32 -> xt hi/lo [b][n][c] bf16 (tile transpose)
// ---------------------------------------------------------------------------
__global__ __launch_bounds__(256) void convert_x_kernel(const float* __restrict__ x)
{
    __shared__ float xs[64][65];
    const int b  = blockIdx.z;
    const int c0 = blockIdx.y * 64;
    const int n0 = blockIdx.x * 64;
    const int tid = threadIdx.x;

#pragma unroll
    for (int i = 0; i < 4; i++) {
        int r = (tid >> 4) + i * 16;
        int col4 = (tid & 15) * 4;
        float4 v = *(const float4*)&x[(size_t)(b * CIN + c0 + r) * HW + n0 + col4];
        xs[r][col4 + 0] = v.x;
        xs[r][col4 + 1] = v.y;
        xs[r][col4 + 2] = v.z;
        xs[r][col4 + 3] = v.w;
    }
    __syncthreads();

    const int n  = tid >> 2;
    const int cs = (tid & 3) * 16;
    u32 hh[8], ll[8];
#pragma unroll
    for (int j = 0; j < 16; j += 2) {
        float a = xs[cs + j][n];
        float b2 = xs[cs + j + 1][n];
        u32 h = packbf(a, b2);
        float2 f = unpackbf(h);
        hh[j >> 1] = h;
        ll[j >> 1] = packbf(a - f.x, b2 - f.y);
    }
    size_t base = ((size_t)(b * HW) + n0 + n) * CIN + c0 + cs;
    *(uint4*)&g_xth[base]     = *(uint4*)&hh[0];
    *(uint4*)&g_xth[base + 8] = *(uint4*)&hh[4];
    *(uint4*)&g_xtl[base]     = *(uint4*)&ll[0];
    *(uint4*)&g_xtl[base + 8] = *(uint4*)&ll[4];
}

// ---------------------------------------------------------------------------
// Kernel 0b: weight conversion -> bf16 hi/lo
// ---------------------------------------------------------------------------
__global__ void convert_w_kernel(const float* __restrict__ wq, const float* __restrict__ wk,
                                 const float* __restrict__ wv, const float* __restrict__ wsa)
{
    const int p = blockIdx.x;
    const float* s = (p == 0) ? wq : (p == 1) ? wk : (p == 2) ? wv : wsa;
    __nv_bfloat16* dh = (p < 3) ? &g_wh[p * DIM * CIN] : g_wsah;
    __nv_bfloat16* dl = (p < 3) ? &g_wl[p * DIM * CIN] : g_wsal;
    for (int i = threadIdx.x; i < DIM * CIN; i += blockDim.x) {
        float v = s[i];
        __nv_bfloat16 h = __float2bfloat16(v);
        dh[i] = h;
        dl[i] = __float2bfloat16(v - __bfloat162float(h));
    }
}

// ---------------------------------------------------------------------------
// Kernel 1: QKV projections via HMMA hi/lo.
// out[n][d] = xt[n][c] . w[d][c]^T + bias.  M=128 (n), N=64 (d), K=256.
// q output pre-scaled by log2(e) so attention uses raw ex2.
// ---------------------------------------------------------------------------
#define QKV_SMEM 196608

__global__ __launch_bounds__(256, 1) void qkv_mma_kernel(
    const float* __restrict__ bq, const float* __restrict__ bk, const float* __restrict__ bv)
{
    extern __shared__ char sm[];
    const u32 sb = smem_u32(sm);
    const int tid  = threadIdx.x;
    const int lane = tid & 31;
    const int wid  = tid >> 5;
    const int wm = wid & 3;
    const int wn = wid >> 2;
    const int g  = lane >> 2;
    const int t  = lane & 3;
    const int b  = blockIdx.y;
    const int p  = blockIdx.z;
    const int i0 = blockIdx.x * 128;
    const float* bias = (p == 0) ? bq : (p == 1) ? bk : bv;
    const float scl = (p == 0) ? LOG2E : 1.0f;

    {
        const char* ah = (const char*)&g_xth[(size_t)(b * HW + i0) * CIN];
        const char* al = (const char*)&g_xtl[(size_t)(b * HW + i0) * CIN];
#pragma unroll
        for (int i = 0; i < 16; i++) {
            int id = tid + i * 256;
            u32 row = (u32)(id >> 5), gg = (u32)(id & 31);
            u32 o = swz512(row, gg);
            u32 so = row * 512 + gg * 16;
            CP16(sb + o, ah + so);
            CP16(sb + 65536 + o, al + so);
        }
        const char* bh = (const char*)&g_wh[p * DIM * CIN];
        const char* bl = (const char*)&g_wl[p * DIM * CIN];
#pragma unroll
        for (int i = 0; i < 8; i++) {
            int id = tid + i * 256;
            u32 row = (u32)(id >> 5), gg = (u32)(id & 31);
            u32 o = swz512(row, gg);
            u32 so = row * 512 + gg * 16;
            CP16(sb + 131072 + o, bh + so);
            CP16(sb + 163840 + o, bl + so);
        }
        CPC(); CPW0();
        __syncthreads();
    }

    float c[2][4][4];
#pragma unroll
    for (int mt = 0; mt < 2; mt++)
#pragma unroll
        for (int nt = 0; nt < 4; nt++)
#pragma unroll
            for (int e = 0; e < 4; e++) c[mt][nt][e] = 0.0f;

    const u32 a_row = wm * 32 + (lane & 15);
    const u32 a_g = (u32)(lane >> 4);
    const u32 b_row = wn * 32 + (lane & 7);
    const u32 b_g = (u32)((lane >> 3) & 1);

#pragma unroll
    for (int kt = 0; kt < 16; kt++) {
        u32 ah2[2][4], al2[2][4];
#pragma unroll
        for (int mt = 0; mt < 2; mt++) {
            u32 off = swz512(a_row + mt * 16, a_g + kt * 2);
            ldsm4(ah2[mt], sb + off);
            ldsm4(al2[mt], sb + 65536 + off);
        }
#pragma unroll
        for (int nt = 0; nt < 4; nt++) {
            u32 bh2[2], bl2[2];
            u32 off = swz512(b_row + nt * 8, b_g + kt * 2);
            ldsm2(bh2, sb + 131072 + off);
            ldsm2(bl2, sb + 163840 + off);
#pragma unroll
            for (int mt = 0; mt < 2; mt++) {
                mma16816(c[mt][nt], ah2[mt], bh2);
                mma16816(c[mt][nt], ah2[mt], bl2);
                mma16816(c[mt][nt], al2[mt], bh2);
            }
        }
    }

    if (p < 2) {
        __nv_bfloat16* oh = (p == 0) ? g_qh : g_kh;
        __nv_bfloat16* ol = (p == 0) ? g_ql : g_kl;
#pragma unroll
        for (int mt = 0; mt < 2; mt++)
#pragma unroll
            for (int nt = 0; nt < 4; nt++) {
                int n = i0 + wm * 32 + mt * 16 + g;
                int d = wn * 32 + nt * 8 + t * 2;
                float b0 = bias[d], b1 = bias[d + 1];
                float v0 = (c[mt][nt][0] + b0) * scl, v1 = (c[mt][nt][1] + b1) * scl;
                float v2 = (c[mt][nt][2] + b0) * scl, v3 = (c[mt][nt][3] + b1) * scl;
                u32 h01 = packbf(v0, v1); float2 f0 = unpackbf(h01);
                u32 l01 = packbf(v0 - f0.x, v1 - f0.y);
                u32 h23 = packbf(v2, v3); float2 f1 = unpackbf(h23);
                u32 l23 = packbf(v2 - f1.x, v3 - f1.y);
                size_t o0 = (size_t)(b * HW + n) * DIM + d;
                size_t o1 = (size_t)(b * HW + n + 8) * DIM + d;
                *(u32*)&oh[o0] = h01; *(u32*)&ol[o0] = l01;
                *(u32*)&oh[o1] = h23; *(u32*)&ol[o1] = l23;
            }
    } else {
        // v: bounce through smem, store hi only
        float* ot = (float*)sm;   // [64 d][128 n]
        __syncthreads();
#pragma unroll
        for (int mt = 0; mt < 2; mt++)
#pragma unroll
            for (int nt = 0; nt < 4; nt++) {
                int n = wm * 32 + mt * 16 + g;
                int d = wn * 32 + nt * 8 + t * 2;
                ot[d * 128 + n]           = c[mt][nt][0];
                ot[(d + 1) * 128 + n]     = c[mt][nt][1];
                ot[d * 128 + n + 8]       = c[mt][nt][2];
                ot[(d + 1) * 128 + n + 8] = c[mt][nt][3];
            }
        __syncthreads();
        int d  = tid >> 2;
        int ns = (tid & 3) * 32;
        float bvv = bias[d];
        u32 hh[16];
#pragma unroll
        for (int j = 0; j < 32; j += 2) {
            float v0 = ot[d * 128 + ns + j] + bvv;
            float v1 = ot[d * 128 + ns + j + 1] + bvv;
            hh[j >> 1] = packbf(v0, v1);
        }
        size_t base = (size_t)(b * DIM + d) * HW + i0 + ns;
#pragma unroll
        for (int q4 = 0; q4 < 4; q4++)
            *(uint4*)&g_vth[base + q4 * 8] = *(uint4*)&hh[q4 * 4];
    }
}

// ---------------------------------------------------------------------------
// Kernel 2: HMMA flash attention. 512 threads = 16 warps (8 M x 2 j-halves).
// S: 3-term hi/lo (exponentiated path, needs precision).
// PV: single product O += ph * vh (both residuals dropped; linear path).
// Smem: Qh 0 (16K) | Ql 16K | buf0 32K..80K | buf1 80K..128K
// ---------------------------------------------------------------------------
#define ATT_BUF0   32768
#define ATT_BUFSZ  49152
#define SM_TOTAL   131072

__device__ __forceinline__ void load_kv(u32 sb, u32 bufbase, int b, int j0, int tid)
{
    const char* kh = (const char*)&g_kh[(size_t)(b * HW + j0) * DIM];
    const char* kl = (const char*)&g_kl[(size_t)(b * HW + j0) * DIM];
#pragma unroll
    for (int i = 0; i < 2; i++) {
        int id = tid + i * 512, row = id >> 3, g = id & 7;
        u32 o = swz128(row, g);
        u32 so = row * 128 + g * 16;
        CP16(sb + bufbase + o, kh + so);
        CP16(sb + bufbase + 16384 + o, kl + so);
    }
    const char* vh = (const char*)&g_vth[(size_t)b * DIM * HW + j0];
#pragma unroll
    for (int i = 0; i < 2; i++) {
        int id = tid + i * 512, d = id >> 4, g = id & 15;
        u32 o = swz256(d, g);
        u32 so = d * (HW * 2) + g * 16;
        CP16(sb + bufbase + 32768 + o, vh + so);
    }
}

__global__ __launch_bounds__(512, 1) void attn_kernel()
{
    extern __shared__ char sm[];
    const u32 sb = smem_u32(sm);
    const int tid  = threadIdx.x;
    const int lane = tid & 31;
    const int wid  = tid >> 5;   // 0..15
    const int wm = wid & 7;      // M group: rows wm*16 .. +15
    const int wn = wid >> 3;     // j half:  cols wn*64 .. +63
    const int b  = blockIdx.y;
    const int i0 = blockIdx.x * 128;
    const int g  = lane >> 2;
    const int t  = lane & 3;

    {
        const char* qh = (const char*)&g_qh[(size_t)(b * HW + i0) * DIM];
        const char* ql = (const char*)&g_ql[(size_t)(b * HW + i0) * DIM];
#pragma unroll
        for (int i = 0; i < 2; i++) {
            int id = tid + i * 512, row = id >> 3, gg = id & 7;
            u32 o = swz128(row, gg);
            u32 so = row * 128 + gg * 16;
            CP16(sb + 0 + o, qh + so);
            CP16(sb + 16384 + o, ql + so);
        }
        load_kv(sb, ATT_BUF0, b, 0, tid);
        CPC();
    }

    float oc[8][4];
    float lsum[2];
    lsum[0] = 0.0f; lsum[1] = 0.0f;
#pragma unroll
    for (int dnt = 0; dnt < 8; dnt++)
#pragma unroll
        for (int e = 0; e < 4; e++) oc[dnt][e] = 0.0f;

    const u32 q_row  = wm * 16 + (lane & 15);
    const u32 q_gsel = (u32)(lane >> 4);
    const u32 b_ro = (u32)(((lane >> 4) << 3) + (lane & 7));
    const u32 b_gg = (u32)((lane >> 3) & 1);

    for (int jt = 0; jt < HW / 128; jt++) {
        CPW0();
        __syncthreads();
        const u32 buf = ATT_BUF0 + (u32)(jt & 1) * ATT_BUFSZ;
        if (jt + 1 < HW / 128)
            load_kv(sb, ATT_BUF0 + (u32)((jt + 1) & 1) * ATT_BUFSZ, b, (jt + 1) * 128, tid);
        CPC();

#pragma unroll
        for (int half = 0; half < 2; half++) {
            // ---- S for 32 j-cols ----
            float sc[4][4];
#pragma unroll
            for (int nt = 0; nt < 4; nt++)
#pragma unroll
                for (int e = 0; e < 4; e++) sc[nt][e] = 0.0f;

#pragma unroll
            for (int kt = 0; kt < 4; kt++) {
                u32 aqh[4], aql[4];
                {
                    u32 off = swz128(q_row, q_gsel + kt * 2);
                    ldsm4(aqh, sb + 0 + off);
                    ldsm4(aql, sb + 16384 + off);
                }
#pragma unroll
                for (int ntp = 0; ntp < 2; ntp++) {
                    u32 bh[4], bl[4];
                    u32 ro = (u32)(wn * 64 + half * 32 + ntp * 16) + b_ro;
                    u32 gg = b_gg + kt * 2;
                    u32 off = swz128(ro, gg);
                    ldsm4(bh, sb + buf + off);
                    ldsm4(bl, sb + buf + 16384 + off);
                    mma16816(sc[ntp * 2 + 0], aqh, bh + 0);
                    mma16816(sc[ntp * 2 + 0], aqh, bl + 0);
                    mma16816(sc[ntp * 2 + 0], aql, bh + 0);
                    mma16816(sc[ntp * 2 + 1], aqh, bh + 2);
                    mma16816(sc[ntp * 2 + 1], aqh, bl + 2);
                    mma16816(sc[ntp * 2 + 1], aql, bh + 2);
                }
            }

            // ---- softmax (ex2, q pre-scaled) + single-product PV ----
#pragma unroll
            for (int jj = 0; jj < 2; jj++) {
                const int jkt = half * 2 + jj;
                u32 ph[4];
#pragma unroll
                for (int h = 0; h < 2; h++) {
                    int nt = jj * 2 + h;
                    float e0 = ex2f(sc[nt][0]);
                    float e1 = ex2f(sc[nt][1]);
                    float e2 = ex2f(sc[nt][2]);
                    float e3 = ex2f(sc[nt][3]);
                    lsum[0] += e0 + e1;
                    lsum[1] += e2 + e3;
                    ph[h * 2 + 0] = packbf(e0, e1);
                    ph[h * 2 + 1] = packbf(e2, e3);
                }
#pragma unroll
                for (int dntp = 0; dntp < 4; dntp++) {
                    u32 bvh[4];
                    u32 ro = (u32)(dntp * 16) + b_ro;
                    u32 gg = (u32)(wn * 8 + jkt * 2) + b_gg;
                    u32 off = swz256(ro, gg);
                    ldsm4(bvh, sb + buf + 32768 + off);
                    mma16816(oc[dntp * 2 + 0], ph, bvh + 0);
                    mma16816(oc[dntp * 2 + 1], ph, bvh + 2);
                }
            }
        }
    }
    __syncthreads();   // protect smem-reuse writes below against last-tile reads

    // ---- epilogue: combine j-half partials, normalize, store hi/lo bf16 ----
    float* lp = (float*)(sm + 65536);   // [wn][128]
#pragma unroll
    for (int r = 0; r < 2; r++) {
        float v = lsum[r];
        v += __shfl_xor_sync(0xffffffffu, v, 1);
        v += __shfl_xor_sync(0xffffffffu, v, 2);
        if (t == 0) lp[wn * 128 + wm * 16 + r * 8 + g] = v;
    }
    float* op = (float*)(sm + wn * 32768);
#pragma unroll
    for (int dnt = 0; dnt < 8; dnt++) {
        int r0 = wm * 16 + g;
        int c = dnt * 8 + t * 2;
        *(float2*)&op[r0 * 64 + c]       = make_float2(oc[dnt][0], oc[dnt][1]);
        *(float2*)&op[(r0 + 8) * 64 + c] = make_float2(oc[dnt][2], oc[dnt][3]);
    }
    __syncthreads();

    float* o0 = (float*)sm;
    float* o1 = (float*)(sm + 32768);
    float* lpf = (float*)(sm + 65536);
#pragma unroll
    for (int i = 0; i < 4; i++) {
        int idx = tid + i * 512;
        int row = idx >> 4, c4 = (idx & 15) * 4;
        float invl = 1.0f / (lpf[row] + lpf[128 + row]);
        float4 a = *(float4*)&o0[row * 64 + c4];
        float4 bb = *(float4*)&o1[row * 64 + c4];
        float v0 = (a.x + bb.x) * invl;
        float v1 = (a.y + bb.y) * invl;
        float v2 = (a.z + bb.z) * invl;
        float v3 = (a.w + bb.w) * invl;
        u32 h01 = packbf(v0, v1); float2 f0 = unpackbf(h01);
        u32 l01 = packbf(v0 - f0.x, v1 - f0.y);
        u32 h23 = packbf(v2, v3); float2 f1 = unpackbf(h23);
        u32 l23 = packbf(v2 - f1.x, v3 - f1.y);
        size_t off = (size_t)(b * HW + i0 + row) * DIM + c4;
        *(uint2*)&g_sah[off] = make_uint2(h01, h23);
        *(uint2*)&g_sal[off] = make_uint2(l01, l23);
    }
}

// ---------------------------------------------------------------------------
// Kernel 3: output projection via HMMA hi/lo + bias + gamma + residual.
// ---------------------------------------------------------------------------
#define PROJ_SMEM 65536

__global__ __launch_bounds__(256, 2) void proj_mma_kernel(
    const float* __restrict__ x,
    const float* __restrict__ bsa,
    const float* __restrict__ gamma,
    float* __restrict__ out)
{
    extern __shared__ char sm[];
    const u32 sb = smem_u32(sm);
    const int tid  = threadIdx.x;
    const int lane = tid & 31;
    const int wid  = tid >> 5;
    const int wm = wid & 3;
    const int wn = wid >> 2;
    const int g  = lane >> 2;
    const int t  = lane & 3;
    const int b  = blockIdx.z;
    const int c0 = blockIdx.y * 128;
    const int n0 = blockIdx.x * 128;

    {
        const char* ah = (const char*)&g_wsah[(size_t)c0 * DIM];
        const char* al = (const char*)&g_wsal[(size_t)c0 * DIM];
        const char* bh = (const char*)&g_sah[(size_t)(b * HW + n0) * DIM];
        const char* bl = (const char*)&g_sal[(size_t)(b * HW + n0) * DIM];
#pragma unroll
        for (int i = 0; i < 4; i++) {
            int id = tid + i * 256;
            u32 row = (u32)(id >> 3), gg = (u32)(id & 7);
            u32 o = swz128(row, gg);
            u32 so = row * 128 + gg * 16;
            CP16(sb + o, ah + so);
            CP16(sb + 16384 + o, al + so);
            CP16(sb + 32768 + o, bh + so);
            CP16(sb + 49152 + o, bl + so);
        }
        CPC(); CPW0();
        __syncthreads();
    }

    float c[2][8][4];
#pragma unroll
    for (int mt = 0; mt < 2; mt++)
#pragma unroll
        for (int nt = 0; nt < 8; nt++)
#pragma unroll
            for (int e = 0; e < 4; e++) c[mt][nt][e] = 0.0f;

    const u32 a_row = wm * 32 + (lane & 15);
    const u32 a_g = (u32)(lane >> 4);
    const u32 b_row = wn * 64 + (lane & 7);
    const u32 b_g = (u32)((lane >> 3) & 1);

#pragma unroll
    for (int kt = 0; kt < 4; kt++) {
        u32 ah2[2][4], al2[2][4];
#pragma unroll
        for (int mt = 0; mt < 2; mt++) {
            u32 off = swz128(a_row + mt * 16, a_g + kt * 2);
            ldsm4(ah2[mt], sb + off);
            ldsm4(al2[mt], sb + 16384 + off);
        }
#pragma unroll
        for (int nt = 0; nt < 8; nt++) {
            u32 bh2[2], bl2[2];
            u32 off = swz128(b_row + nt * 8, b_g + kt * 2);
            ldsm2(bh2, sb + 32768 + off);
            ldsm2(bl2, sb + 49152 + off);
#pragma unroll
            for (int mt = 0; mt < 2; mt++) {
                mma16816(c[mt][nt], ah2[mt], bh2);
                mma16816(c[mt][nt], ah2[mt], bl2);
                mma16816(c[mt][nt], al2[mt], bh2);
            }
        }
    }

    const float gm = gamma[0];
#pragma unroll
    for (int mt = 0; mt < 2; mt++)
#pragma unroll
        for (int nt = 0; nt < 8; nt++) {
            int cg = c0 + wm * 32 + mt * 16 + g;
            int n  = n0 + wn * 64 + nt * 8 + t * 2;
            float b0 = bsa[cg], b1 = bsa[cg + 8];
            size_t off0 = ((size_t)(b * CIN) + cg) * HW + n;
            size_t off1 = off0 + (size_t)8 * HW;
            float2 xv0 = *(const float2*)&x[off0];
            float2 xv1 = *(const float2*)&x[off1];
            float2 o0, o1;
            o0.x = gm * (c[mt][nt][0] + b0) + xv0.x;
            o0.y = gm * (c[mt][nt][1] + b0) + xv0.y;
            o1.x = gm * (c[mt][nt][2] + b1) + xv1.x;
            o1.y = gm * (c[mt][nt][3] + b1) + xv1.y;
            *(float2*)&out[off0] = o0;
            *(float2*)&out[off1] = o1;
        }
}

// ---------------------------------------------------------------------------
extern "C" void kernel_launch(void* const* d_in, const int* in_sizes, int n_in,
                              void* d_out, int out_size)
{
    const float* x     = (const float*)d_in[0];
    const float* wq    = (const float*)d_in[1];
    const float* bq    = (const float*)d_in[2];
    const float* wk    = (const float*)d_in[3];
    const float* bk    = (const float*)d_in[4];
    const float* wv    = (const float*)d_in[5];
    const float* bv    = (const float*)d_in[6];
    const float* wsa   = (const float*)d_in[7];
    const float* bsa   = (const float*)d_in[8];
    const float* gamma = (const float*)d_in[9];
    float* out = (float*)d_out;

    cudaFuncSetAttribute(attn_kernel, cudaFuncAttributeMaxDynamicSharedMemorySize, SM_TOTAL);
    cudaFuncSetAttribute(qkv_mma_kernel, cudaFuncAttributeMaxDynamicSharedMemorySize, QKV_SMEM);
    cudaFuncSetAttribute(proj_mma_kernel, cudaFuncAttributeMaxDynamicSharedMemorySize, PROJ_SMEM);

    convert_x_kernel<<<dim3(HW / 64, CIN / 64, BATCH), 256>>>(x);
    convert_w_kernel<<<4, 256>>>(wq, wk, wv, wsa);
    qkv_mma_kernel<<<dim3(HW / 128, BATCH, 3), 256, QKV_SMEM>>>(bq, bk, bv);
    attn_kernel<<<dim3(HW / 128, BATCH), 512, SM_TOTAL>>>();
    proj_mma_kernel<<<dim3(HW / 128, CIN / 128, BATCH), 256, PROJ_SMEM>>>(x, bsa, gamma, out);
}

// round 10
// speedup vs baseline: 1.3571x; 1.0481x over previous
#include <cuda_runtime.h>
#include <cuda_bf16.h>
#include <math.h>
#include <stdint.h>
#include <string.h>

#define BATCH 4
#define CIN   256
#define HW    4096
#define DIM   64
#define LOG2E 1.4426950408889634f

typedef unsigned int u32;
typedef unsigned long long u64;

// ---------------------------------------------------------------------------
// Device scratch
// ---------------------------------------------------------------------------
__device__ __nv_bfloat16 g_xth[BATCH * HW * CIN];   // x transposed [b][n][c] hi
__device__ __nv_bfloat16 g_xtl[BATCH * HW * CIN];   // lo
__device__ __nv_bfloat16 g_wh[3 * DIM * CIN];       // wq|wk|wv hi
__device__ __nv_bfloat16 g_wl[3 * DIM * CIN];
__device__ __nv_bfloat16 g_wsah[CIN * DIM];
__device__ __nv_bfloat16 g_wsal[CIN * DIM];
__device__ __nv_bfloat16 g_qh[BATCH * HW * DIM];    // q pre-scaled by log2(e)
__device__ __nv_bfloat16 g_ql[BATCH * HW * DIM];
__device__ __nv_bfloat16 g_kh[BATCH * HW * DIM];
__device__ __nv_bfloat16 g_kl[BATCH * HW * DIM];
__device__ __nv_bfloat16 g_vth[BATCH * DIM * HW];   // [b][d][j] (hi only)
__device__ __nv_bfloat16 g_sah[BATCH * HW * DIM];   // attention out [b][n][d]
__device__ __nv_bfloat16 g_sal[BATCH * HW * DIM];

// ---------------------------------------------------------------------------
// Helpers
// ---------------------------------------------------------------------------
__device__ __forceinline__ uint32_t smem_u32(const void* p) {
    uint32_t a;
    asm("{ .reg .u64 t; cvta.to.shared.u64 t, %1; cvt.u32.u64 %0, t; }" : "=r"(a) : "l"(p));
    return a;
}
// pack two floats into bf16x2: lo -> bits[15:0], hi -> bits[31:16]
__device__ __forceinline__ u32 packbf(float lo, float hi) {
    u32 r;
    asm("cvt.rn.bf16x2.f32 %0, %1, %2;" : "=r"(r) : "f"(hi), "f"(lo));
    return r;
}
__device__ __forceinline__ float2 unpackbf(u32 u) {
    __nv_bfloat162 h;
    memcpy(&h, &u, 4);
    return make_float2(__bfloat162float(h.x), __bfloat162float(h.y));
}
__device__ __forceinline__ float ex2f(float x) {
    float r;
    asm("ex2.approx.f32 %0, %1;" : "=f"(r) : "f"(x));
    return r;
}
__device__ __forceinline__ void mma16816(float* c, const u32* a, const u32* b) {
    asm volatile(
        "mma.sync.aligned.m16n8k16.row.col.f32.bf16.bf16.f32 "
        "{%0,%1,%2,%3}, {%4,%5,%6,%7}, {%8,%9}, {%0,%1,%2,%3};"
        : "+f"(c[0]), "+f"(c[1]), "+f"(c[2]), "+f"(c[3])
        : "r"(a[0]), "r"(a[1]), "r"(a[2]), "r"(a[3]), "r"(b[0]), "r"(b[1]));
}
__device__ __forceinline__ void ldsm4(u32* r, uint32_t addr) {
    asm volatile("ldmatrix.sync.aligned.m8n8.x4.shared.b16 {%0,%1,%2,%3}, [%4];"
        : "=r"(r[0]), "=r"(r[1]), "=r"(r[2]), "=r"(r[3]) : "r"(addr));
}
__device__ __forceinline__ void ldsm2(u32* r, uint32_t addr) {
    asm volatile("ldmatrix.sync.aligned.m8n8.x2.shared.b16 {%0,%1}, [%2];"
        : "=r"(r[0]), "=r"(r[1]) : "r"(addr));
}
#define CP16(dst, src) asm volatile("cp.async.cg.shared.global [%0], [%1], 16;" :: "r"(dst), "l"(src))
#define CPC()  asm volatile("cp.async.commit_group;")
#define CPW0() asm volatile("cp.async.wait_group 0;")

// XOR swizzles for 128B / 256B / 512B rows (16B granules)
__device__ __forceinline__ u32 swz128(u32 row, u32 g) { return row * 128u + ((g ^ (row & 7u)) << 4); }
__device__ __forceinline__ u32 swz256(u32 row, u32 g) { return row * 256u + (((g & 8u) | ((g & 7u) ^ (row & 7u))) << 4); }
__device__ __forceinline__ u32 swz512(u32 row, u32 g) { return row * 512u + (((g & 24u) | ((g & 7u) ^ (row & 7u))) << 4); }

// ---------------------------------------------------------------------------
// Kernel 0a: x [b][c][n] fp32 -> xt hi/lo [b][n][c] bf16 (tile transpose)
// ---------------------------------------------------------------------------
__global__ __launch_bounds__(256) void convert_x_kernel(const float* __restrict__ x)
{
    __shared__ float xs[64][65];
    const int b  = blockIdx.z;
    const int c0 = blockIdx.y * 64;
    const int n0 = blockIdx.x * 64;
    const int tid = threadIdx.x;

#pragma unroll
    for (int i = 0; i < 4; i++) {
        int r = (tid >> 4) + i * 16;
        int col4 = (tid & 15) * 4;
        float4 v = *(const float4*)&x[(size_t)(b * CIN + c0 + r) * HW + n0 + col4];
        xs[r][col4 + 0] = v.x;
        xs[r][col4 + 1] = v.y;
        xs[r][col4 + 2] = v.z;
        xs[r][col4 + 3] = v.w;
    }
    __syncthreads();

    const int n  = tid >> 2;
    const int cs = (tid & 3) * 16;
    u32 hh[8], ll[8];
#pragma unroll
    for (int j = 0; j < 16; j += 2) {
        float a = xs[cs + j][n];
        float b2 = xs[cs + j + 1][n];
        u32 h = packbf(a, b2);
        float2 f = unpackbf(h);
        hh[j >> 1] = h;
        ll[j >> 1] = packbf(a - f.x, b2 - f.y);
    }
    size_t base = ((size_t)(b * HW) + n0 + n) * CIN + c0 + cs;
    *(uint4*)&g_xth[base]     = *(uint4*)&hh[0];
    *(uint4*)&g_xth[base + 8] = *(uint4*)&hh[4];
    *(uint4*)&g_xtl[base]     = *(uint4*)&ll[0];
    *(uint4*)&g_xtl[base + 8] = *(uint4*)&ll[4];
}

// ---------------------------------------------------------------------------
// Kernel 0b: weight conversion -> bf16 hi/lo
// ---------------------------------------------------------------------------
__global__ void convert_w_kernel(const float* __restrict__ wq, const float* __restrict__ wk,
                                 const float* __restrict__ wv, const float* __restrict__ wsa)
{
    const int p = blockIdx.x;
    const float* s = (p == 0) ? wq : (p == 1) ? wk : (p == 2) ? wv : wsa;
    __nv_bfloat16* dh = (p < 3) ? &g_wh[p * DIM * CIN] : g_wsah;
    __nv_bfloat16* dl = (p < 3) ? &g_wl[p * DIM * CIN] : g_wsal;
    for (int i = threadIdx.x; i < DIM * CIN; i += blockDim.x) {
        float v = s[i];
        __nv_bfloat16 h = __float2bfloat16(v);
        dh[i] = h;
        dl[i] = __float2bfloat16(v - __bfloat162float(h));
    }
}

// ---------------------------------------------------------------------------
// Kernel 1: QKV projections via HMMA hi/lo.
// out[n][d] = xt[n][c] . w[d][c]^T + bias.  M=128 (n), N=64 (d), K=256.
// q output pre-scaled by log2(e) so attention uses raw ex2.
// ---------------------------------------------------------------------------
#define QKV_SMEM 196608

__global__ __launch_bounds__(256, 1) void qkv_mma_kernel(
    const float* __restrict__ bq, const float* __restrict__ bk, const float* __restrict__ bv)
{
    extern __shared__ char sm[];
    const u32 sb = smem_u32(sm);
    const int tid  = threadIdx.x;
    const int lane = tid & 31;
    const int wid  = tid >> 5;
    const int wm = wid & 3;
    const int wn = wid >> 2;
    const int g  = lane >> 2;
    const int t  = lane & 3;
    const int b  = blockIdx.y;
    const int p  = blockIdx.z;
    const int i0 = blockIdx.x * 128;
    const float* bias = (p == 0) ? bq : (p == 1) ? bk : bv;
    const float scl = (p == 0) ? LOG2E : 1.0f;

    {
        const char* ah = (const char*)&g_xth[(size_t)(b * HW + i0) * CIN];
        const char* al = (const char*)&g_xtl[(size_t)(b * HW + i0) * CIN];
#pragma unroll
        for (int i = 0; i < 16; i++) {
            int id = tid + i * 256;
            u32 row = (u32)(id >> 5), gg = (u32)(id & 31);
            u32 o = swz512(row, gg);
            u32 so = row * 512 + gg * 16;
            CP16(sb + o, ah + so);
            CP16(sb + 65536 + o, al + so);
        }
        const char* bh = (const char*)&g_wh[p * DIM * CIN];
        const char* bl = (const char*)&g_wl[p * DIM * CIN];
#pragma unroll
        for (int i = 0; i < 8; i++) {
            int id = tid + i * 256;
            u32 row = (u32)(id >> 5), gg = (u32)(id & 31);
            u32 o = swz512(row, gg);
            u32 so = row * 512 + gg * 16;
            CP16(sb + 131072 + o, bh + so);
            CP16(sb + 163840 + o, bl + so);
        }
        CPC(); CPW0();
        __syncthreads();
    }

    float c[2][4][4];
#pragma unroll
    for (int mt = 0; mt < 2; mt++)
#pragma unroll
        for (int nt = 0; nt < 4; nt++)
#pragma unroll
            for (int e = 0; e < 4; e++) c[mt][nt][e] = 0.0f;

    const u32 a_row = wm * 32 + (lane & 15);
    const u32 a_g = (u32)(lane >> 4);
    const u32 b_row = wn * 32 + (lane & 7);
    const u32 b_g = (u32)((lane >> 3) & 1);

#pragma unroll
    for (int kt = 0; kt < 16; kt++) {
        u32 ah2[2][4], al2[2][4];
#pragma unroll
        for (int mt = 0; mt < 2; mt++) {
            u32 off = swz512(a_row + mt * 16, a_g + kt * 2);
            ldsm4(ah2[mt], sb + off);
            ldsm4(al2[mt], sb + 65536 + off);
        }
#pragma unroll
        for (int nt = 0; nt < 4; nt++) {
            u32 bh2[2], bl2[2];
            u32 off = swz512(b_row + nt * 8, b_g + kt * 2);
            ldsm2(bh2, sb + 131072 + off);
            ldsm2(bl2, sb + 163840 + off);
#pragma unroll
            for (int mt = 0; mt < 2; mt++) {
                mma16816(c[mt][nt], ah2[mt], bh2);
                mma16816(c[mt][nt], ah2[mt], bl2);
                mma16816(c[mt][nt], al2[mt], bh2);
            }
        }
    }

    if (p < 2) {
        __nv_bfloat16* oh = (p == 0) ? g_qh : g_kh;
        __nv_bfloat16* ol = (p == 0) ? g_ql : g_kl;
#pragma unroll
        for (int mt = 0; mt < 2; mt++)
#pragma unroll
            for (int nt = 0; nt < 4; nt++) {
                int n = i0 + wm * 32 + mt * 16 + g;
                int d = wn * 32 + nt * 8 + t * 2;
                float b0 = bias[d], b1 = bias[d + 1];
                float v0 = (c[mt][nt][0] + b0) * scl, v1 = (c[mt][nt][1] + b1) * scl;
                float v2 = (c[mt][nt][2] + b0) * scl, v3 = (c[mt][nt][3] + b1) * scl;
                u32 h01 = packbf(v0, v1); float2 f0 = unpackbf(h01);
                u32 l01 = packbf(v0 - f0.x, v1 - f0.y);
                u32 h23 = packbf(v2, v3); float2 f1 = unpackbf(h23);
                u32 l23 = packbf(v2 - f1.x, v3 - f1.y);
                size_t o0 = (size_t)(b * HW + n) * DIM + d;
                size_t o1 = (size_t)(b * HW + n + 8) * DIM + d;
                *(u32*)&oh[o0] = h01; *(u32*)&ol[o0] = l01;
                *(u32*)&oh[o1] = h23; *(u32*)&ol[o1] = l23;
            }
    } else {
        // v: bounce through smem, store hi only
        float* ot = (float*)sm;   // [64 d][128 n]
        __syncthreads();
#pragma unroll
        for (int mt = 0; mt < 2; mt++)
#pragma unroll
            for (int nt = 0; nt < 4; nt++) {
                int n = wm * 32 + mt * 16 + g;
                int d = wn * 32 + nt * 8 + t * 2;
                ot[d * 128 + n]           = c[mt][nt][0];
                ot[(d + 1) * 128 + n]     = c[mt][nt][1];
                ot[d * 128 + n + 8]       = c[mt][nt][2];
                ot[(d + 1) * 128 + n + 8] = c[mt][nt][3];
            }
        __syncthreads();
        int d  = tid >> 2;
        int ns = (tid & 3) * 32;
        float bvv = bias[d];
        u32 hh[16];
#pragma unroll
        for (int j = 0; j < 32; j += 2) {
            float v0 = ot[d * 128 + ns + j] + bvv;
            float v1 = ot[d * 128 + ns + j + 1] + bvv;
            hh[j >> 1] = packbf(v0, v1);
        }
        size_t base = (size_t)(b * DIM + d) * HW + i0 + ns;
#pragma unroll
        for (int q4 = 0; q4 < 4; q4++)
            *(uint4*)&g_vth[base + q4 * 8] = *(uint4*)&hh[q4 * 4];
    }
}

// ---------------------------------------------------------------------------
// Kernel 2: HMMA flash attention. 256 threads = 8 warps (4 M-groups of 32
// rows x 2 j-halves of 64). Q FRAGMENTS REGISTER-RESIDENT across the whole
// j sweep (no Q ldmatrix in the mainloop). S 3-term, PV single-product.
// Smem: Qh 0 (16K) | Ql 16K | buf0 32K..80K | buf1 80K..128K
// ---------------------------------------------------------------------------
#define ATT_BUF0   32768
#define ATT_BUFSZ  49152
#define SM_TOTAL   131072

__device__ __forceinline__ void load_kv(u32 sb, u32 bufbase, int b, int j0, int tid)
{
    const char* kh = (const char*)&g_kh[(size_t)(b * HW + j0) * DIM];
    const char* kl = (const char*)&g_kl[(size_t)(b * HW + j0) * DIM];
#pragma unroll
    for (int i = 0; i < 4; i++) {
        int id = tid + i * 256, row = id >> 3, g = id & 7;
        u32 o = swz128(row, g);
        u32 so = row * 128 + g * 16;
        CP16(sb + bufbase + o, kh + so);
        CP16(sb + bufbase + 16384 + o, kl + so);
    }
    const char* vh = (const char*)&g_vth[(size_t)b * DIM * HW + j0];
#pragma unroll
    for (int i = 0; i < 4; i++) {
        int id = tid + i * 256, d = id >> 4, g = id & 15;
        u32 o = swz256(d, g);
        u32 so = d * (HW * 2) + g * 16;
        CP16(sb + bufbase + 32768 + o, vh + so);
    }
}

__global__ __launch_bounds__(256, 1) void attn_kernel()
{
    extern __shared__ char sm[];
    const u32 sb = smem_u32(sm);
    const int tid  = threadIdx.x;
    const int lane = tid & 31;
    const int wid  = tid >> 5;   // 0..7
    const int wm = wid & 3;      // M group: rows wm*32 .. +31
    const int wn = wid >> 2;     // j half:  cols wn*64 .. +63
    const int b  = blockIdx.y;
    const int i0 = blockIdx.x * 128;
    const int g  = lane >> 2;
    const int t  = lane & 3;

    {
        const char* qh = (const char*)&g_qh[(size_t)(b * HW + i0) * DIM];
        const char* ql = (const char*)&g_ql[(size_t)(b * HW + i0) * DIM];
#pragma unroll
        for (int i = 0; i < 4; i++) {
            int id = tid + i * 256, row = id >> 3, gg = id & 7;
            u32 o = swz128(row, gg);
            u32 so = row * 128 + gg * 16;
            CP16(sb + 0 + o, qh + so);
            CP16(sb + 16384 + o, ql + so);
        }
        load_kv(sb, ATT_BUF0, b, 0, tid);
        CPC(); CPW0();
        __syncthreads();
    }

    // ---- Load Q fragments once; resident for the whole sweep ----
    u32 qfh[4][2][4], qfl[4][2][4];
    {
        const u32 q_row  = wm * 32 + (lane & 15);
        const u32 q_gsel = (u32)(lane >> 4);
#pragma unroll
        for (int kt = 0; kt < 4; kt++)
#pragma unroll
            for (int mt = 0; mt < 2; mt++) {
                u32 off = swz128(q_row + mt * 16, q_gsel + kt * 2);
                ldsm4(qfh[kt][mt], sb + 0 + off);
                ldsm4(qfl[kt][mt], sb + 16384 + off);
            }
    }

    float oc[2][8][4];
    float lsum[2][2];
#pragma unroll
    for (int mt = 0; mt < 2; mt++) {
        lsum[mt][0] = 0.0f; lsum[mt][1] = 0.0f;
#pragma unroll
        for (int dnt = 0; dnt < 8; dnt++)
#pragma unroll
            for (int e = 0; e < 4; e++) oc[mt][dnt][e] = 0.0f;
    }

    const u32 b_ro = (u32)(((lane >> 4) << 3) + (lane & 7));
    const u32 b_gg = (u32)((lane >> 3) & 1);

    for (int jt = 0; jt < HW / 128; jt++) {
        CPW0();
        __syncthreads();
        const u32 buf = ATT_BUF0 + (u32)(jt & 1) * ATT_BUFSZ;
        if (jt + 1 < HW / 128)
            load_kv(sb, ATT_BUF0 + (u32)((jt + 1) & 1) * ATT_BUFSZ, b, (jt + 1) * 128, tid);
        CPC();

#pragma unroll
        for (int half = 0; half < 2; half++) {
            // ---- S for 32 j-cols x 32 m-rows ----
            float sc[2][4][4];
#pragma unroll
            for (int mt = 0; mt < 2; mt++)
#pragma unroll
                for (int nt = 0; nt < 4; nt++)
#pragma unroll
                    for (int e = 0; e < 4; e++) sc[mt][nt][e] = 0.0f;

#pragma unroll
            for (int kt = 0; kt < 4; kt++) {
#pragma unroll
                for (int ntp = 0; ntp < 2; ntp++) {
                    u32 bh[4], bl[4];
                    u32 ro = (u32)(wn * 64 + half * 32 + ntp * 16) + b_ro;
                    u32 gg = b_gg + kt * 2;
                    u32 off = swz128(ro, gg);
                    ldsm4(bh, sb + buf + off);
                    ldsm4(bl, sb + buf + 16384 + off);
#pragma unroll
                    for (int mt = 0; mt < 2; mt++) {
                        mma16816(sc[mt][ntp * 2 + 0], qfh[kt][mt], bh + 0);
                        mma16816(sc[mt][ntp * 2 + 0], qfh[kt][mt], bl + 0);
                        mma16816(sc[mt][ntp * 2 + 0], qfl[kt][mt], bh + 0);
                        mma16816(sc[mt][ntp * 2 + 1], qfh[kt][mt], bh + 2);
                        mma16816(sc[mt][ntp * 2 + 1], qfh[kt][mt], bl + 2);
                        mma16816(sc[mt][ntp * 2 + 1], qfl[kt][mt], bh + 2);
                    }
                }
            }

            // ---- softmax (ex2) + single-product PV, two 16-wide chunks ----
#pragma unroll
            for (int jj = 0; jj < 2; jj++) {
                const int jkt = half * 2 + jj;
                u32 ph[2][4];
#pragma unroll
                for (int mt = 0; mt < 2; mt++) {
#pragma unroll
                    for (int h = 0; h < 2; h++) {
                        int nt = jj * 2 + h;
                        float e0 = ex2f(sc[mt][nt][0]);
                        float e1 = ex2f(sc[mt][nt][1]);
                        float e2 = ex2f(sc[mt][nt][2]);
                        float e3 = ex2f(sc[mt][nt][3]);
                        lsum[mt][0] += e0 + e1;
                        lsum[mt][1] += e2 + e3;
                        ph[mt][h * 2 + 0] = packbf(e0, e1);
                        ph[mt][h * 2 + 1] = packbf(e2, e3);
                    }
                }
#pragma unroll
                for (int dntp = 0; dntp < 4; dntp++) {
                    u32 bvh[4];
                    u32 ro = (u32)(dntp * 16) + b_ro;
                    u32 gg = (u32)(wn * 8 + jkt * 2) + b_gg;
                    u32 off = swz256(ro, gg);
                    ldsm4(bvh, sb + buf + 32768 + off);
#pragma unroll
                    for (int mt = 0; mt < 2; mt++) {
                        mma16816(oc[mt][dntp * 2 + 0], ph[mt], bvh + 0);
                        mma16816(oc[mt][dntp * 2 + 1], ph[mt], bvh + 2);
                    }
                }
            }
        }
    }
    __syncthreads();   // protect smem-reuse writes below against last-tile reads

    // ---- epilogue: combine j-half partials, normalize, store hi/lo bf16 ----
    float* lp = (float*)(sm + 65536);   // [wn][128]
#pragma unroll
    for (int mt = 0; mt < 2; mt++)
#pragma unroll
        for (int r = 0; r < 2; r++) {
            float v = lsum[mt][r];
            v += __shfl_xor_sync(0xffffffffu, v, 1);
            v += __shfl_xor_sync(0xffffffffu, v, 2);
            if (t == 0) lp[wn * 128 + wm * 32 + mt * 16 + r * 8 + g] = v;
        }
    float* op = (float*)(sm + wn * 32768);
#pragma unroll
    for (int mt = 0; mt < 2; mt++)
#pragma unroll
        for (int dnt = 0; dnt < 8; dnt++) {
            int r0 = wm * 32 + mt * 16 + g;
            int c = dnt * 8 + t * 2;
            *(float2*)&op[r0 * 64 + c]       = make_float2(oc[mt][dnt][0], oc[mt][dnt][1]);
            *(float2*)&op[(r0 + 8) * 64 + c] = make_float2(oc[mt][dnt][2], oc[mt][dnt][3]);
        }
    __syncthreads();

    float* o0 = (float*)sm;
    float* o1 = (float*)(sm + 32768);
    float* lpf = (float*)(sm + 65536);
#pragma unroll
    for (int i = 0; i < 8; i++) {
        int idx = tid + i * 256;
        int row = idx >> 4, c4 = (idx & 15) * 4;
        float invl = 1.0f / (lpf[row] + lpf[128 + row]);
        float4 a = *(float4*)&o0[row * 64 + c4];
        float4 bb = *(float4*)&o1[row * 64 + c4];
        float v0 = (a.x + bb.x) * invl;
        float v1 = (a.y + bb.y) * invl;
        float v2 = (a.z + bb.z) * invl;
        float v3 = (a.w + bb.w) * invl;
        u32 h01 = packbf(v0, v1); float2 f0 = unpackbf(h01);
        u32 l01 = packbf(v0 - f0.x, v1 - f0.y);
        u32 h23 = packbf(v2, v3); float2 f1 = unpackbf(h23);
        u32 l23 = packbf(v2 - f1.x, v3 - f1.y);
        size_t off = (size_t)(b * HW + i0 + row) * DIM + c4;
        *(uint2*)&g_sah[off] = make_uint2(h01, h23);
        *(uint2*)&g_sal[off] = make_uint2(l01, l23);
    }
}

// ---------------------------------------------------------------------------
// Kernel 3: output projection via HMMA hi/lo + bias + gamma + residual.
// ---------------------------------------------------------------------------
#define PROJ_SMEM 65536

__global__ __launch_bounds__(256, 2) void proj_mma_kernel(
    const float* __restrict__ x,
    const float* __restrict__ bsa,
    const float* __restrict__ gamma,
    float* __restrict__ out)
{
    extern __shared__ char sm[];
    const u32 sb = smem_u32(sm);
    const int tid  = threadIdx.x;
    const int lane = tid & 31;
    const int wid  = tid >> 5;
    const int wm = wid & 3;
    const int wn = wid >> 2;
    const int g  = lane >> 2;
    const int t  = lane & 3;
    const int b  = blockIdx.z;
    const int c0 = blockIdx.y * 128;
    const int n0 = blockIdx.x * 128;

    {
        const char* ah = (const char*)&g_wsah[(size_t)c0 * DIM];
        const char* al = (const char*)&g_wsal[(size_t)c0 * DIM];
        const char* bh = (const char*)&g_sah[(size_t)(b * HW + n0) * DIM];
        const char* bl = (const char*)&g_sal[(size_t)(b * HW + n0) * DIM];
#pragma unroll
        for (int i = 0; i < 4; i++) {
            int id = tid + i * 256;
            u32 row = (u32)(id >> 3), gg = (u32)(id & 7);
            u32 o = swz128(row, gg);
            u32 so = row * 128 + gg * 16;
            CP16(sb + o, ah + so);
            CP16(sb + 16384 + o, al + so);
            CP16(sb + 32768 + o, bh + so);
            CP16(sb + 49152 + o, bl + so);
        }
        CPC(); CPW0();
        __syncthreads();
    }

    float c[2][8][4];
#pragma unroll
    for (int mt = 0; mt < 2; mt++)
#pragma unroll
        for (int nt = 0; nt < 8; nt++)
#pragma unroll
            for (int e = 0; e < 4; e++) c[mt][nt][e] = 0.0f;

    const u32 a_row = wm * 32 + (lane & 15);
    const u32 a_g = (u32)(lane >> 4);
    const u32 b_row = wn * 64 + (lane & 7);
    const u32 b_g = (u32)((lane >> 3) & 1);

#pragma unroll
    for (int kt = 0; kt < 4; kt++) {
        u32 ah2[2][4], al2[2][4];
#pragma unroll
        for (int mt = 0; mt < 2; mt++) {
            u32 off = swz128(a_row + mt * 16, a_g + kt * 2);
            ldsm4(ah2[mt], sb + off);
            ldsm4(al2[mt], sb + 16384 + off);
        }
#pragma unroll
        for (int nt = 0; nt < 8; nt++) {
            u32 bh2[2], bl2[2];
            u32 off = swz128(b_row + nt * 8, b_g + kt * 2);
            ldsm2(bh2, sb + 32768 + off);
            ldsm2(bl2, sb + 49152 + off);
#pragma unroll
            for (int mt = 0; mt < 2; mt++) {
                mma16816(c[mt][nt], ah2[mt], bh2);
                mma16816(c[mt][nt], ah2[mt], bl2);
                mma16816(c[mt][nt], al2[mt], bh2);
            }
        }
    }

    const float gm = gamma[0];
#pragma unroll
    for (int mt = 0; mt < 2; mt++)
#pragma unroll
        for (int nt = 0; nt < 8; nt++) {
            int cg = c0 + wm * 32 + mt * 16 + g;
            int n  = n0 + wn * 64 + nt * 8 + t * 2;
            float b0 = bsa[cg], b1 = bsa[cg + 8];
            size_t off0 = ((size_t)(b * CIN) + cg) * HW + n;
            size_t off1 = off0 + (size_t)8 * HW;
            float2 xv0 = *(const float2*)&x[off0];
            float2 xv1 = *(const float2*)&x[off1];
            float2 o0, o1;
            o0.x = gm * (c[mt][nt][0] + b0) + xv0.x;
            o0.y = gm * (c[mt][nt][1] + b0) + xv0.y;
            o1.x = gm * (c[mt][nt][2] + b1) + xv1.x;
            o1.y = gm * (c[mt][nt][3] + b1) + xv1.y;
            *(float2*)&out[off0] = o0;
            *(float2*)&out[off1] = o1;
        }
}

// ---------------------------------------------------------------------------
extern "C" void kernel_launch(void* const* d_in, const int* in_sizes, int n_in,
                              void* d_out, int out_size)
{
    const float* x     = (const float*)d_in[0];
    const float* wq    = (const float*)d_in[1];
    const float* bq    = (const float*)d_in[2];
    const float* wk    = (const float*)d_in[3];
    const float* bk    = (const float*)d_in[4];
    const float* wv    = (const float*)d_in[5];
    const float* bv    = (const float*)d_in[6];
    const float* wsa   = (const float*)d_in[7];
    const float* bsa   = (const float*)d_in[8];
    const float* gamma = (const float*)d_in[9];
    float* out = (float*)d_out;

    cudaFuncSetAttribute(attn_kernel, cudaFuncAttributeMaxDynamicSharedMemorySize, SM_TOTAL);
    cudaFuncSetAttribute(qkv_mma_kernel, cudaFuncAttributeMaxDynamicSharedMemorySize, QKV_SMEM);
    cudaFuncSetAttribute(proj_mma_kernel, cudaFuncAttributeMaxDynamicSharedMemorySize, PROJ_SMEM);

    convert_x_kernel<<<dim3(HW / 64, CIN / 64, BATCH), 256>>>(x);
    convert_w_kernel<<<4, 256>>>(wq, wk, wv, wsa);
    qkv_mma_kernel<<<dim3(HW / 128, BATCH, 3), 256, QKV_SMEM>>>(bq, bk, bv);
    attn_kernel<<<dim3(HW / 128, BATCH), 256, SM_TOTAL>>>();
    proj_mma_kernel<<<dim3(HW / 128, CIN / 128, BATCH), 256, PROJ_SMEM>>>(x, bsa, gamma, out);
}